// round 4
// baseline (speedup 1.0000x reference)
#include <cuda_runtime.h>
#include <cuda_fp16.h>
#include <math.h>
#include <stdint.h>

#define D_MODEL 1024
#define NHEAD   16
#define DH      64
#define BATCH   2
#define SEQ     2048
#define MROWS   (BATCH*SEQ)   // 4096
#define BHN     (BATCH*NHEAD) // 32

// Scratch (allocation-free): head-major [BHN, SEQ, DH] fp32 buffers.
__device__ float g_Q[BHN * SEQ * DH];
__device__ float g_K[BHN * SEQ * DH];
__device__ float g_V[BHN * SEQ * DH];
__device__ float g_O[BHN * SEQ * DH];

// ---------------------------------------------------------------------------
// helpers
// ---------------------------------------------------------------------------
__device__ __forceinline__ uint32_t pack2(float a, float b) {
    __half2 h = __floats2half2_rn(a, b);   // .x = a (low), .y = b (high)
    return *reinterpret_cast<uint32_t*>(&h);
}

// D += A(16x8x16 row) * B(16x8 col) ; fp16 in, fp32 accumulate
__device__ __forceinline__ void mma16(float* c, const uint32_t* a,
                                      uint32_t b0, uint32_t b1) {
    asm volatile(
        "mma.sync.aligned.m16n8k16.row.col.f32.f16.f16.f32 "
        "{%0,%1,%2,%3}, {%4,%5,%6,%7}, {%8,%9}, {%0,%1,%2,%3};"
        : "+f"(c[0]), "+f"(c[1]), "+f"(c[2]), "+f"(c[3])
        : "r"(a[0]), "r"(a[1]), "r"(a[2]), "r"(a[3]), "r"(b0), "r"(b1));
}

// ---------------------------------------------------------------------------
// fp16 tensor GEMM: C[4096,1024] = A @ W (+bias)*alpha
// mode 0/1/2: A = x, scatter head-major into g_Q/g_K/g_V; mode 3: A from g_O.
// CTA 128x128, BK=32, double buffered fp16 smem. 8 warps (2x4), warp 64x32.
// As[row][k] stride 20 words (40 fp16); Ws[n][k] stride 20 words (W transposed
// in-quad at store so b-frags are k-contiguous LDS.32).
// ---------------------------------------------------------------------------
#define BK   32
#define NS   (D_MODEL / BK)   // 32
#define AST  20                // u32 words per A row
#define WST  20
#define BUFW (128*AST + 128*WST)   // 5120 words per buffer

__global__ __launch_bounds__(256, 2) void tc_gemm_kernel(
    const float* __restrict__ A, const float* __restrict__ W,
    const float* __restrict__ bias, float* __restrict__ Cout,
    int mode, float alpha)
{
    __shared__ uint32_t sm[2 * BUFW];   // 40 KB

    const int tid  = threadIdx.x;
    const int w    = tid >> 5, lane = tid & 31;
    const int g    = lane >> 2, t = lane & 3;
    const int wm   = w >> 2, wn = w & 3;
    const int m0w  = wm * 64, n0w = wn * 32;
    const int bm   = blockIdx.y * 128, bn = blockIdx.x * 128;
    const int bb   = bm >> 11;

    uint2  pa[4];
    float4 pw[4];

    auto ldgA = [&](int kt) {
        #pragma unroll
        for (int i = 0; i < 4; i++) {
            int idx = tid + 256 * i;
            int row = idx >> 3, c4 = (idx & 7) * 4;
            const float* src;
            if (mode < 3) {
                src = A + (size_t)(bm + row) * D_MODEL + kt + c4;
            } else {
                int h = kt >> 6;
                int tt = (bm + row) & (SEQ - 1);
                src = g_O + (((size_t)(bb * NHEAD + h)) * SEQ + tt) * DH
                      + (kt & 63) + c4;
            }
            float4 v = *(const float4*)src;
            pa[i] = make_uint2(pack2(v.x, v.y), pack2(v.z, v.w));
        }
    };
    auto ldgW = [&](int kt) {
        #pragma unroll
        for (int i = 0; i < 4; i++) {
            int T = i * 64 + (tid >> 2);
            int kq = T & 7, nq = T >> 3;
            pw[i] = *(const float4*)(W + (size_t)(kt + kq * 4 + t) * D_MODEL
                                     + bn + nq * 4);
        }
    };
    auto stsA = [&](uint32_t* dst) {
        #pragma unroll
        for (int i = 0; i < 4; i++) {
            int idx = tid + 256 * i;
            int row = idx >> 3, c4 = (idx & 7) * 4;
            *(uint2*)&dst[row * AST + (c4 >> 1)] = pa[i];
        }
    };
    auto stsW = [&](uint32_t* dst) {   // dst = Ws base; in-quad 4x4 transpose
        #pragma unroll
        for (int i = 0; i < 4; i++) {
            int T = i * 64 + (tid >> 2);
            int kq = T & 7, nq = T >> 3;
            float t0, t1, t2, t3;
            #pragma unroll
            for (int j = 0; j < 4; j++) {
                int es = (t + j) & 3;
                float val = es == 0 ? pw[i].x : es == 1 ? pw[i].y
                          : es == 2 ? pw[i].z : pw[i].w;
                int sl = (t - j) & 3;
                float got = __shfl_sync(0xffffffffu, val, (lane & ~3) | sl);
                if      (sl == 0) t0 = got;
                else if (sl == 1) t1 = got;
                else if (sl == 2) t2 = got;
                else              t3 = got;
            }
            // lane t holds col n = nq*4 + t, rows k = kq*4 .. kq*4+3
            *(uint2*)&dst[(nq * 4 + t) * WST + kq * 2] =
                make_uint2(pack2(t0, t1), pack2(t2, t3));
        }
    };

    ldgA(0); ldgW(0);
    stsA(sm); stsW(sm + 128 * AST);
    __syncthreads();

    float acc[4][4][4] = {};

    #pragma unroll 1
    for (int s = 0; s < NS; s++) {
        const int buf = s & 1;
        if (s + 1 < NS) { ldgA((s + 1) * BK); ldgW((s + 1) * BK); }

        uint32_t* As_ = sm + buf * BUFW;
        uint32_t* Ws_ = As_ + 128 * AST;

        #pragma unroll
        for (int ks = 0; ks < 2; ks++) {     // two k16 steps per BK=32
            const int wb = ks * 8;
            uint32_t a[4][4];
            #pragma unroll
            for (int mt = 0; mt < 4; mt++) {
                int r = m0w + mt * 16 + g;
                a[mt][0] = As_[r * AST + wb + t];
                a[mt][1] = As_[(r + 8) * AST + wb + t];
                a[mt][2] = As_[r * AST + wb + 4 + t];
                a[mt][3] = As_[(r + 8) * AST + wb + 4 + t];
            }
            #pragma unroll
            for (int nt = 0; nt < 4; nt++) {
                int n = n0w + nt * 8 + g;
                uint32_t b0 = Ws_[n * WST + wb + t];
                uint32_t b1 = Ws_[n * WST + wb + 4 + t];
                #pragma unroll
                for (int mt = 0; mt < 4; mt++)
                    mma16(acc[mt][nt], a[mt], b0, b1);
            }
        }
        __syncthreads();
        if (s + 1 < NS) {
            uint32_t* Ad = sm + (buf ^ 1) * BUFW;
            stsA(Ad); stsW(Ad + 128 * AST);
            __syncthreads();
        }
    }

    // Epilogue
    float* outp = (mode == 0) ? g_Q : (mode == 1) ? g_K : g_V;
    #pragma unroll
    for (int mt = 0; mt < 4; mt++) {
        #pragma unroll
        for (int nt = 0; nt < 4; nt++) {
            int rl = m0w + mt * 16 + g;
            int cl = n0w + nt * 8 + t * 2;
            float2 bv = *(const float2*)&bias[bn + cl];
            float2 o0, o1;
            o0.x = (acc[mt][nt][0] + bv.x) * alpha;
            o0.y = (acc[mt][nt][1] + bv.y) * alpha;
            o1.x = (acc[mt][nt][2] + bv.x) * alpha;
            o1.y = (acc[mt][nt][3] + bv.y) * alpha;
            if (mode == 3) {
                *(float2*)&Cout[(size_t)(bm + rl) * D_MODEL + bn + cl] = o0;
                *(float2*)&Cout[(size_t)(bm + rl + 8) * D_MODEL + bn + cl] = o1;
            } else {
                int col = bn + cl;
                int h = col >> 6, d = col & 63;
                int t0r = (bm + rl) & (SEQ - 1);
                float* ob = outp + ((size_t)(bb * NHEAD + h)) * SEQ * DH;
                *(float2*)&ob[(size_t)t0r * DH + d] = o0;
                *(float2*)&ob[(size_t)(t0r + 8) * DH + d] = o1;
            }
        }
    }
}

// ---------------------------------------------------------------------------
// Flash attention, fp16 MMA. CTA = 128 queries, 8 warps x 16-row slabs,
// KV tiles of 64. Q frags in registers. K smem [key][d], V smem [d][key]
// (quad-transposed), P smem [q][key], all stride 36 words (72 fp16).
// ---------------------------------------------------------------------------
#define FST 36   // u32 words per row

__global__ __launch_bounds__(256, 2) void flash_kernel()
{
    __shared__ uint32_t Ks[64 * FST];    // 9216 B
    __shared__ uint32_t Vs[64 * FST];    // 9216 B
    __shared__ uint32_t Ps[128 * FST];   // 18432 B

    const int tid = threadIdx.x;
    const int w = tid >> 5, lane = tid & 31;
    const int g = lane >> 2, t = lane & 3;
    const int bh = blockIdx.y;
    const int q0 = blockIdx.x * 128;

    const float* Qp = g_Q + ((size_t)bh * SEQ + q0) * DH;
    const float* Kp = g_K + (size_t)bh * SEQ * DH;
    const float* Vp = g_V + (size_t)bh * SEQ * DH;

    const int lr = w * 16 + g;   // local q-row (this thread's m16 row)

    // Q fragments in registers: 4 k16-steps x 4 regs.
    uint32_t qf[4][4];
    {
        const float* qr0 = Qp + (size_t)lr * DH;
        const float* qr8 = qr0 + 8 * DH;
        #pragma unroll
        for (int s = 0; s < 4; s++) {
            int k = s * 16 + 2 * t;
            float2 v0 = *(const float2*)(qr0 + k);
            float2 v1 = *(const float2*)(qr8 + k);
            float2 v2 = *(const float2*)(qr0 + k + 8);
            float2 v3 = *(const float2*)(qr8 + k + 8);
            qf[s][0] = pack2(v0.x, v0.y);
            qf[s][1] = pack2(v1.x, v1.y);
            qf[s][2] = pack2(v2.x, v2.y);
            qf[s][3] = pack2(v3.x, v3.y);
        }
    }

    float o[8][4] = {};
    float m0 = -INFINITY, m1 = -INFINITY, l0 = 0.f, l1 = 0.f;

    #pragma unroll 1
    for (int kt = 0; kt < SEQ; kt += 64) {
        __syncthreads();
        // K tile: [key][d] fp16
        #pragma unroll
        for (int i = 0; i < 4; i++) {
            int idx = i * 256 + tid;
            int key = idx >> 4, c4 = (idx & 15) * 4;
            float4 kv = *(const float4*)(Kp + (size_t)(kt + key) * DH + c4);
            *(uint2*)&Ks[key * FST + (c4 >> 1)] =
                make_uint2(pack2(kv.x, kv.y), pack2(kv.z, kv.w));
        }
        // V tile: transposed to [d][key] fp16 via in-quad 4x4 transpose
        #pragma unroll
        for (int i = 0; i < 4; i++) {
            int r = i * 64 + (tid >> 2);
            int key0 = (r & 15) * 4, d0 = (r >> 4) * 4;
            float4 v = *(const float4*)(Vp + (size_t)(kt + key0 + t) * DH + d0);
            float t0, t1, t2, t3;
            #pragma unroll
            for (int j = 0; j < 4; j++) {
                int es = (t + j) & 3;
                float val = es == 0 ? v.x : es == 1 ? v.y
                          : es == 2 ? v.z : v.w;
                int sl = (t - j) & 3;
                float got = __shfl_sync(0xffffffffu, val, (lane & ~3) | sl);
                if      (sl == 0) t0 = got;
                else if (sl == 1) t1 = got;
                else if (sl == 2) t2 = got;
                else              t3 = got;
            }
            // lane t holds V[key0..key0+3][d0+t]
            *(uint2*)&Vs[(d0 + t) * FST + (key0 >> 1)] =
                make_uint2(pack2(t0, t1), pack2(t2, t3));
        }
        __syncthreads();

        // S = Q @ K^T : 4 k16-steps x 8 key-tiles
        float s_[8][4] = {};
        #pragma unroll
        for (int s = 0; s < 4; s++) {
            #pragma unroll
            for (int nt = 0; nt < 8; nt++) {
                uint32_t b0 = Ks[(nt * 8 + g) * FST + s * 8 + t];
                uint32_t b1 = Ks[(nt * 8 + g) * FST + s * 8 + 4 + t];
                mma16(s_[nt], qf[s], b0, b1);
            }
        }

        // online softmax (rows lr -> regs 0/1, lr+8 -> regs 2/3)
        float mx0 = -INFINITY, mx1 = -INFINITY;
        #pragma unroll
        for (int nt = 0; nt < 8; nt++) {
            mx0 = fmaxf(mx0, fmaxf(s_[nt][0], s_[nt][1]));
            mx1 = fmaxf(mx1, fmaxf(s_[nt][2], s_[nt][3]));
        }
        mx0 = fmaxf(mx0, __shfl_xor_sync(0xffffffffu, mx0, 1));
        mx0 = fmaxf(mx0, __shfl_xor_sync(0xffffffffu, mx0, 2));
        mx1 = fmaxf(mx1, __shfl_xor_sync(0xffffffffu, mx1, 1));
        mx1 = fmaxf(mx1, __shfl_xor_sync(0xffffffffu, mx1, 2));

        float mn0 = fmaxf(m0, mx0), mn1 = fmaxf(m1, mx1);
        float c0 = __expf(m0 - mn0), c1 = __expf(m1 - mn1);
        m0 = mn0; m1 = mn1;

        float sum0 = 0.f, sum1 = 0.f;
        #pragma unroll
        for (int nt = 0; nt < 8; nt++) {
            s_[nt][0] = __expf(s_[nt][0] - mn0); sum0 += s_[nt][0];
            s_[nt][1] = __expf(s_[nt][1] - mn0); sum0 += s_[nt][1];
            s_[nt][2] = __expf(s_[nt][2] - mn1); sum1 += s_[nt][2];
            s_[nt][3] = __expf(s_[nt][3] - mn1); sum1 += s_[nt][3];
        }
        sum0 += __shfl_xor_sync(0xffffffffu, sum0, 1);
        sum0 += __shfl_xor_sync(0xffffffffu, sum0, 2);
        sum1 += __shfl_xor_sync(0xffffffffu, sum1, 1);
        sum1 += __shfl_xor_sync(0xffffffffu, sum1, 2);
        l0 = l0 * c0 + sum0;
        l1 = l1 * c1 + sum1;

        #pragma unroll
        for (int nt = 0; nt < 8; nt++) {
            o[nt][0] *= c0; o[nt][1] *= c0;
            o[nt][2] *= c1; o[nt][3] *= c1;
        }

        // P -> smem fp16 [q][key]
        __syncwarp();
        #pragma unroll
        for (int nt = 0; nt < 8; nt++) {
            Ps[lr * FST + nt * 4 + t]       = pack2(s_[nt][0], s_[nt][1]);
            Ps[(lr + 8) * FST + nt * 4 + t] = pack2(s_[nt][2], s_[nt][3]);
        }
        __syncwarp();

        // O += P @ V : 4 k16-steps (64 keys) x 8 d-tiles
        #pragma unroll
        for (int s = 0; s < 4; s++) {
            uint32_t a[4];
            a[0] = Ps[lr * FST + 8 * s + t];
            a[1] = Ps[(lr + 8) * FST + 8 * s + t];
            a[2] = Ps[lr * FST + 8 * s + 4 + t];
            a[3] = Ps[(lr + 8) * FST + 8 * s + 4 + t];
            #pragma unroll
            for (int nt = 0; nt < 8; nt++) {
                uint32_t b0 = Vs[(nt * 8 + g) * FST + 8 * s + t];
                uint32_t b1 = Vs[(nt * 8 + g) * FST + 8 * s + 4 + t];
                mma16(o[nt], a, b0, b1);
            }
        }
    }

    // epilogue
    float inv0 = 1.0f / l0, inv1 = 1.0f / l1;
    float* Op = g_O + ((size_t)bh * SEQ + q0) * DH;
    #pragma unroll
    for (int nt = 0; nt < 8; nt++) {
        int col = nt * 8 + t * 2;
        *(float2*)&Op[(size_t)lr * DH + col] =
            make_float2(o[nt][0] * inv0, o[nt][1] * inv0);
        *(float2*)&Op[(size_t)(lr + 8) * DH + col] =
            make_float2(o[nt][2] * inv1, o[nt][3] * inv1);
    }
}

// ---------------------------------------------------------------------------
extern "C" void kernel_launch(void* const* d_in, const int* in_sizes, int n_in,
                              void* d_out, int out_size)
{
    const float* x  = (const float*)d_in[0];
    const float* Wq = (const float*)d_in[1];
    const float* bq = (const float*)d_in[2];
    const float* Wk = (const float*)d_in[3];
    const float* bk = (const float*)d_in[4];
    const float* Wv = (const float*)d_in[5];
    const float* bv = (const float*)d_in[6];
    const float* Wo = (const float*)d_in[7];
    const float* bo = (const float*)d_in[8];
    (void)in_sizes; (void)n_in; (void)out_size;

    dim3 gg(D_MODEL / 128, MROWS / 128);  // (8, 32)

    const float scale = 0.125f;  // 1/sqrt(DH) folded into Q projection
    tc_gemm_kernel<<<gg, 256>>>(x, Wq, bq, nullptr, 0, scale);
    tc_gemm_kernel<<<gg, 256>>>(x, Wk, bk, nullptr, 1, 1.0f);
    tc_gemm_kernel<<<gg, 256>>>(x, Wv, bv, nullptr, 2, 1.0f);

    flash_kernel<<<dim3(SEQ / 128, BHN), 256>>>();

    tc_gemm_kernel<<<gg, 256>>>(x, Wo, bo, (float*)d_out, 3, 1.0f);
}

// round 5
// speedup vs baseline: 2.9953x; 2.9953x over previous
#include <cuda_runtime.h>
#include <cuda_fp16.h>
#include <math.h>
#include <stdint.h>

#define D_MODEL 1024
#define NHEAD   16
#define DH      64
#define BATCH   2
#define SEQ     2048
#define MROWS   (BATCH*SEQ)   // 4096
#define BHN     (BATCH*NHEAD) // 32

// Scratch (allocation-free): fp16 buffers.
__device__ __align__(16) __half g_Qh[BHN * SEQ * DH];
__device__ __align__(16) __half g_Kh[BHN * SEQ * DH];
__device__ __align__(16) __half g_Vh[BHN * SEQ * DH];
__device__ __align__(16) __half g_Oh[BHN * SEQ * DH];
__device__ __align__(16) __half g_xh[MROWS * D_MODEL];
__device__ __align__(16) __half g_Wt[4][D_MODEL * D_MODEL];  // [n][k] fp16

// ---------------------------------------------------------------------------
// helpers
// ---------------------------------------------------------------------------
__device__ __forceinline__ uint32_t pack2(float a, float b) {
    __half2 h = __floats2half2_rn(a, b);
    return *reinterpret_cast<uint32_t*>(&h);
}
__device__ __forceinline__ uint32_t smem_u32(const void* p) {
    uint32_t r;
    asm("{ .reg .u64 t; cvta.to.shared.u64 t, %1; cvt.u32.u64 %0, t; }"
        : "=r"(r) : "l"(p));
    return r;
}
__device__ __forceinline__ void mma16(float* c, const uint32_t* a,
                                      uint32_t b0, uint32_t b1) {
    asm volatile(
        "mma.sync.aligned.m16n8k16.row.col.f32.f16.f16.f32 "
        "{%0,%1,%2,%3}, {%4,%5,%6,%7}, {%8,%9}, {%0,%1,%2,%3};"
        : "+f"(c[0]), "+f"(c[1]), "+f"(c[2]), "+f"(c[3])
        : "r"(a[0]), "r"(a[1]), "r"(a[2]), "r"(a[3]), "r"(b0), "r"(b1));
}
__device__ __forceinline__ void ldm_x4(uint32_t* r, uint32_t addr) {
    asm volatile("ldmatrix.sync.aligned.m8n8.x4.shared.b16 {%0,%1,%2,%3}, [%4];"
        : "=r"(r[0]), "=r"(r[1]), "=r"(r[2]), "=r"(r[3]) : "r"(addr));
}
__device__ __forceinline__ void ldm_x4_t(uint32_t* r, uint32_t addr) {
    asm volatile("ldmatrix.sync.aligned.m8n8.x4.trans.shared.b16 {%0,%1,%2,%3}, [%4];"
        : "=r"(r[0]), "=r"(r[1]), "=r"(r[2]), "=r"(r[3]) : "r"(addr));
}

// ---------------------------------------------------------------------------
// Pre-pass: x (f32) -> g_xh (f16)
// ---------------------------------------------------------------------------
__global__ __launch_bounds__(256) void conv_x_kernel(const float* __restrict__ x)
{
    int idx = blockIdx.x * 256 + threadIdx.x;   // 1M threads, 4 elems each
    float4 v = *(const float4*)(x + (size_t)idx * 4);
    uint2 u = make_uint2(pack2(v.x, v.y), pack2(v.z, v.w));
    *(uint2*)(g_xh + (size_t)idx * 4) = u;
}

// ---------------------------------------------------------------------------
// Pre-pass: W [k][n] f32 -> g_Wt[sel] [n][k] f16. 32x32 tiles via smem.
// ---------------------------------------------------------------------------
__global__ __launch_bounds__(256) void transpose_w_kernel(
    const float* __restrict__ W, int sel)
{
    __shared__ float tile[32][33];
    const int tx = threadIdx.x & 31, ty = threadIdx.x >> 5;  // (32, 8)
    const int k0 = blockIdx.y * 32, n0 = blockIdx.x * 32;
    #pragma unroll
    for (int j = 0; j < 4; j++)
        tile[ty + 8 * j][tx] = W[(size_t)(k0 + ty + 8 * j) * D_MODEL + n0 + tx];
    __syncthreads();
    __half* Wt = g_Wt[sel];
    #pragma unroll
    for (int jj = 0; jj < 2; jj++) {
        int w_ = threadIdx.x + 256 * jj;   // 0..511
        int n = w_ >> 4, c = w_ & 15;
        uint32_t u = pack2(tile[2 * c][n], tile[2 * c + 1][n]);
        *(uint32_t*)(Wt + (size_t)(n0 + n) * D_MODEL + k0 + 2 * c) = u;
    }
}

// ---------------------------------------------------------------------------
// fp16 tensor GEMM: C[4096,1024] = A @ W (+bias)*alpha
// A from g_xh (modes 0-2) or g_Oh head-major (mode 3); B from g_Wt[sel] [n][k].
// CTA 128x128, BK=32 halves, double buffered. 8 warps (2x4), warp 64x32.
// Frags via ldmatrix.x4. Smem rows: 32 halves = 16 words + 4 pad = stride 20.
// ---------------------------------------------------------------------------
#define BK   32
#define NS   (D_MODEL / BK)   // 32
#define GST  20                // u32 words per smem row
#define BUFW (128*GST + 128*GST)   // 5120 words / buffer

__global__ __launch_bounds__(256, 2) void tc_gemm_kernel(
    const __half* __restrict__ Wt, const float* __restrict__ bias,
    float* __restrict__ Cout, int mode, float alpha)
{
    __shared__ uint32_t sm[2 * BUFW];   // 40 KB

    const int tid  = threadIdx.x;
    const int w    = tid >> 5, lane = tid & 31;
    const int g    = lane >> 2, t = lane & 3;
    const int wm   = w >> 2, wn = w & 3;
    const int m0w  = wm * 64, n0w = wn * 32;
    const int bm   = blockIdx.y * 128, bn = blockIdx.x * 128;
    const int bb   = bm >> 11;

    uint4 pa[2], pw[2];

    auto ldgA = [&](int kt) {
        #pragma unroll
        for (int i = 0; i < 2; i++) {
            int idx = tid + 256 * i;           // 0..511
            int row = idx >> 2, seg = idx & 3; // 4 x 16B per row
            const __half* src;
            if (mode < 3) {
                src = g_xh + (size_t)(bm + row) * D_MODEL + kt + seg * 8;
            } else {
                int h = kt >> 6;
                int tt = (bm + row) & (SEQ - 1);
                src = g_Oh + (((size_t)(bb * NHEAD + h)) * SEQ + tt) * DH
                      + (kt & 63) + seg * 8;
            }
            pa[i] = *(const uint4*)src;
        }
    };
    auto ldgW = [&](int kt) {
        #pragma unroll
        for (int i = 0; i < 2; i++) {
            int idx = tid + 256 * i;
            int row = idx >> 2, seg = idx & 3;
            pw[i] = *(const uint4*)(Wt + (size_t)(bn + row) * D_MODEL
                                    + kt + seg * 8);
        }
    };
    auto stsAll = [&](uint32_t* dst) {
        #pragma unroll
        for (int i = 0; i < 2; i++) {
            int idx = tid + 256 * i;
            int row = idx >> 2, seg = idx & 3;
            *(uint4*)&dst[row * GST + seg * 4] = pa[i];
            *(uint4*)&dst[128 * GST + row * GST + seg * 4] = pw[i];
        }
    };

    const uint32_t smb = smem_u32(sm);
    // per-lane ldmatrix address components
    const int lrow = lane & 7;
    const int a_roff = ((lane >> 3) & 1) * 8;   // A: m0/m2 -> +0, m1/m3 -> +8
    const int a_coff = (lane >> 4) * 4;         // A: m0/m1 -> +0, m2/m3 -> +4w
    const int b_roff = (lane >> 4) * 8;         // B: m0/m1 -> +0, m2/m3 -> +8
    const int b_coff = ((lane >> 3) & 1) * 4;   // B: m0/m2 -> +0, m1/m3 -> +4w

    ldgA(0); ldgW(0);
    stsAll(sm);
    __syncthreads();

    float acc[4][4][4] = {};

    #pragma unroll 1
    for (int s = 0; s < NS; s++) {
        const int buf = s & 1;
        if (s + 1 < NS) { ldgA((s + 1) * BK); ldgW((s + 1) * BK); }

        const uint32_t ab = smb + buf * (BUFW * 4);
        const uint32_t wb = ab + 128 * GST * 4;

        #pragma unroll
        for (int ks = 0; ks < 2; ks++) {
            const int k0w = ks * 8;
            uint32_t a[4][4], b[2][4];
            #pragma unroll
            for (int mt = 0; mt < 4; mt++)
                ldm_x4(a[mt], ab + ((m0w + mt * 16 + a_roff + lrow) * GST
                                    + k0w + a_coff) * 4);
            #pragma unroll
            for (int np = 0; np < 2; np++)
                ldm_x4(b[np], wb + ((n0w + np * 16 + b_roff + lrow) * GST
                                    + k0w + b_coff) * 4);
            #pragma unroll
            for (int nt = 0; nt < 4; nt++) {
                uint32_t b0 = b[nt >> 1][(nt & 1) * 2];
                uint32_t b1 = b[nt >> 1][(nt & 1) * 2 + 1];
                #pragma unroll
                for (int mt = 0; mt < 4; mt++)
                    mma16(acc[mt][nt], a[mt], b0, b1);
            }
        }
        __syncthreads();
        if (s + 1 < NS) {
            stsAll(sm + (buf ^ 1) * BUFW);
            __syncthreads();
        }
    }

    // Epilogue
    __half* outp = (mode == 0) ? g_Qh : (mode == 1) ? g_Kh : g_Vh;
    #pragma unroll
    for (int mt = 0; mt < 4; mt++) {
        #pragma unroll
        for (int nt = 0; nt < 4; nt++) {
            int rl = m0w + mt * 16 + g;
            int cl = n0w + nt * 8 + t * 2;
            float2 bv = *(const float2*)&bias[bn + cl];
            float v00 = (acc[mt][nt][0] + bv.x) * alpha;
            float v01 = (acc[mt][nt][1] + bv.y) * alpha;
            float v10 = (acc[mt][nt][2] + bv.x) * alpha;
            float v11 = (acc[mt][nt][3] + bv.y) * alpha;
            if (mode == 3) {
                *(float2*)&Cout[(size_t)(bm + rl) * D_MODEL + bn + cl] =
                    make_float2(v00, v01);
                *(float2*)&Cout[(size_t)(bm + rl + 8) * D_MODEL + bn + cl] =
                    make_float2(v10, v11);
            } else {
                int col = bn + cl;
                int h = col >> 6, d = col & 63;
                int t0r = (bm + rl) & (SEQ - 1);
                __half* ob = outp + ((size_t)(bb * NHEAD + h)) * SEQ * DH;
                *(uint32_t*)&ob[(size_t)t0r * DH + d] = pack2(v00, v01);
                *(uint32_t*)&ob[(size_t)(t0r + 8) * DH + d] = pack2(v10, v11);
            }
        }
    }
}

// ---------------------------------------------------------------------------
// Flash attention, fp16 MMA + ldmatrix. CTA = 128 queries, 8 warps x 16 rows,
// KV tiles of 64 keys. Q frags in regs, P frags in regs (QK C-frag == PV
// A-frag layout). K frags: ldmatrix.x4; V frags: ldmatrix.x4.trans.
// Smem rows: 64 halves = 32 words + 4 pad = stride 36.
// ---------------------------------------------------------------------------
#define FST 36

__global__ __launch_bounds__(256, 2) void flash_kernel()
{
    __shared__ uint32_t Ks[64 * FST];   // 9216 B
    __shared__ uint32_t Vs[64 * FST];   // 9216 B

    const int tid = threadIdx.x;
    const int w = tid >> 5, lane = tid & 31;
    const int g = lane >> 2, t = lane & 3;
    const int bh = blockIdx.y;
    const int q0 = blockIdx.x * 128;

    const __half* Qp = g_Qh + ((size_t)bh * SEQ + q0) * DH;
    const __half* Kp = g_Kh + (size_t)bh * SEQ * DH;
    const __half* Vp = g_Vh + (size_t)bh * SEQ * DH;

    const int lr = w * 16 + g;

    // Q fragments in registers (scale already folded in projection).
    uint32_t qf[4][4];
    #pragma unroll
    for (int s = 0; s < 4; s++) {
        qf[s][0] = *(const uint32_t*)(Qp + (size_t)lr * DH + s * 16 + 2 * t);
        qf[s][1] = *(const uint32_t*)(Qp + (size_t)(lr + 8) * DH + s * 16 + 2 * t);
        qf[s][2] = *(const uint32_t*)(Qp + (size_t)lr * DH + s * 16 + 8 + 2 * t);
        qf[s][3] = *(const uint32_t*)(Qp + (size_t)(lr + 8) * DH + s * 16 + 8 + 2 * t);
    }

    const uint32_t ksb = smem_u32(Ks), vsb = smem_u32(Vs);
    // per-lane ldmatrix address parts
    const int lrow = lane & 7;
    const uint32_t k_lane = ksb + (lrow * FST + (lane >> 3) * 4) * 4;   // K x4
    const uint32_t v_lane = vsb + ((((lane >> 3) & 1) * 8 + lrow) * FST
                                   + (lane >> 4) * 4) * 4;              // V x4.trans

    float o[8][4] = {};
    float m0 = -INFINITY, m1 = -INFINITY, l0 = 0.f, l1 = 0.f;

    #pragma unroll 1
    for (int kt = 0; kt < SEQ; kt += 64) {
        __syncthreads();
        #pragma unroll
        for (int i = 0; i < 2; i++) {
            int idx = i * 256 + tid;            // 0..511
            int row = idx >> 3, seg = idx & 7;  // 8 x 16B per row
            *(uint4*)&Ks[row * FST + seg * 4] =
                *(const uint4*)(Kp + (size_t)(kt + row) * DH + seg * 8);
            *(uint4*)&Vs[row * FST + seg * 4] =
                *(const uint4*)(Vp + (size_t)(kt + row) * DH + seg * 8);
        }
        __syncthreads();

        // S = Q @ K^T
        float s_[8][4] = {};
        #pragma unroll
        for (int nt = 0; nt < 8; nt++) {
            uint32_t kb[4], kb2[4];
            uint32_t base = k_lane + nt * 8 * (FST * 4);
            ldm_x4(kb,  base);            // b0,b1 for k-steps 0,1 (d 0..31)
            ldm_x4(kb2, base + 16 * 4);   // k-steps 2,3 (d 32..63)
            mma16(s_[nt], qf[0], kb[0],  kb[1]);
            mma16(s_[nt], qf[1], kb[2],  kb[3]);
            mma16(s_[nt], qf[2], kb2[0], kb2[1]);
            mma16(s_[nt], qf[3], kb2[2], kb2[3]);
        }

        // online softmax (rows lr -> regs 0/1, lr+8 -> regs 2/3)
        float mx0 = -INFINITY, mx1 = -INFINITY;
        #pragma unroll
        for (int nt = 0; nt < 8; nt++) {
            mx0 = fmaxf(mx0, fmaxf(s_[nt][0], s_[nt][1]));
            mx1 = fmaxf(mx1, fmaxf(s_[nt][2], s_[nt][3]));
        }
        mx0 = fmaxf(mx0, __shfl_xor_sync(0xffffffffu, mx0, 1));
        mx0 = fmaxf(mx0, __shfl_xor_sync(0xffffffffu, mx0, 2));
        mx1 = fmaxf(mx1, __shfl_xor_sync(0xffffffffu, mx1, 1));
        mx1 = fmaxf(mx1, __shfl_xor_sync(0xffffffffu, mx1, 2));

        float mn0 = fmaxf(m0, mx0), mn1 = fmaxf(m1, mx1);
        float c0 = __expf(m0 - mn0), c1 = __expf(m1 - mn1);
        m0 = mn0; m1 = mn1;

        float sum0 = 0.f, sum1 = 0.f;
        #pragma unroll
        for (int nt = 0; nt < 8; nt++) {
            s_[nt][0] = __expf(s_[nt][0] - mn0); sum0 += s_[nt][0];
            s_[nt][1] = __expf(s_[nt][1] - mn0); sum0 += s_[nt][1];
            s_[nt][2] = __expf(s_[nt][2] - mn1); sum1 += s_[nt][2];
            s_[nt][3] = __expf(s_[nt][3] - mn1); sum1 += s_[nt][3];
        }
        sum0 += __shfl_xor_sync(0xffffffffu, sum0, 1);
        sum0 += __shfl_xor_sync(0xffffffffu, sum0, 2);
        sum1 += __shfl_xor_sync(0xffffffffu, sum1, 1);
        sum1 += __shfl_xor_sync(0xffffffffu, sum1, 2);
        l0 = l0 * c0 + sum0;
        l1 = l1 * c1 + sum1;

        #pragma unroll
        for (int nt = 0; nt < 8; nt++) {
            o[nt][0] *= c0; o[nt][1] *= c0;
            o[nt][2] *= c1; o[nt][3] *= c1;
        }

        // P frags in registers: QK C-frag == PV A-frag after f16 packing.
        uint32_t pf[4][4];
        #pragma unroll
        for (int s = 0; s < 4; s++) {
            pf[s][0] = pack2(s_[2 * s][0],     s_[2 * s][1]);
            pf[s][1] = pack2(s_[2 * s][2],     s_[2 * s][3]);
            pf[s][2] = pack2(s_[2 * s + 1][0], s_[2 * s + 1][1]);
            pf[s][3] = pack2(s_[2 * s + 1][2], s_[2 * s + 1][3]);
        }

        // O += P @ V : V frags via ldmatrix.trans on row-major [key][d]
        #pragma unroll
        for (int s = 0; s < 4; s++) {
            uint32_t base = v_lane + s * 16 * (FST * 4);
            #pragma unroll
            for (int np = 0; np < 4; np++) {
                uint32_t vb[4];
                ldm_x4_t(vb, base + np * 8 * 4);   // d-tiles 2np, 2np+1
                mma16(o[2 * np],     pf[s], vb[0], vb[1]);
                mma16(o[2 * np + 1], pf[s], vb[2], vb[3]);
            }
        }
    }

    // epilogue -> g_Oh (fp16 head-major)
    float inv0 = 1.0f / l0, inv1 = 1.0f / l1;
    __half* Op = g_Oh + ((size_t)bh * SEQ + q0) * DH;
    #pragma unroll
    for (int nt = 0; nt < 8; nt++) {
        int col = nt * 8 + t * 2;
        *(uint32_t*)&Op[(size_t)lr * DH + col] =
            pack2(o[nt][0] * inv0, o[nt][1] * inv0);
        *(uint32_t*)&Op[(size_t)(lr + 8) * DH + col] =
            pack2(o[nt][2] * inv1, o[nt][3] * inv1);
    }
}

// ---------------------------------------------------------------------------
extern "C" void kernel_launch(void* const* d_in, const int* in_sizes, int n_in,
                              void* d_out, int out_size)
{
    const float* x  = (const float*)d_in[0];
    const float* Wq = (const float*)d_in[1];
    const float* bq = (const float*)d_in[2];
    const float* Wk = (const float*)d_in[3];
    const float* bk = (const float*)d_in[4];
    const float* Wv = (const float*)d_in[5];
    const float* bv = (const float*)d_in[6];
    const float* Wo = (const float*)d_in[7];
    const float* bo = (const float*)d_in[8];
    (void)in_sizes; (void)n_in; (void)out_size;

    // pre-passes
    conv_x_kernel<<<MROWS * D_MODEL / 1024, 256>>>(x);
    dim3 tg(D_MODEL / 32, D_MODEL / 32);
    transpose_w_kernel<<<tg, 256>>>(Wq, 0);
    transpose_w_kernel<<<tg, 256>>>(Wk, 1);
    transpose_w_kernel<<<tg, 256>>>(Wv, 2);
    transpose_w_kernel<<<tg, 256>>>(Wo, 3);

    dim3 gg(D_MODEL / 128, MROWS / 128);  // (8, 32)
    const float scale = 0.125f;  // 1/sqrt(DH) folded into Q projection

    // device-symbol addresses for Wt: pass via a small trick — kernels index
    // g_Wt directly by sel through a pointer parameter fetched on device.
    // Simplest: take address on device via separate launches with sel-specific
    // pointer obtained from the symbol (host cannot take device address without
    // cudaGetSymbolAddress, which is allowed — it's not an allocation).
    static __half* wt_base = nullptr;
    if (!wt_base) {
        void* p = nullptr;
        cudaGetSymbolAddress(&p, g_Wt);
        wt_base = (__half*)p;
    }
    const size_t WSZ = (size_t)D_MODEL * D_MODEL;

    tc_gemm_kernel<<<gg, 256>>>(wt_base + 0 * WSZ, bq, nullptr, 0, scale);
    tc_gemm_kernel<<<gg, 256>>>(wt_base + 1 * WSZ, bk, nullptr, 1, 1.0f);
    tc_gemm_kernel<<<gg, 256>>>(wt_base + 2 * WSZ, bv, nullptr, 2, 1.0f);

    flash_kernel<<<dim3(SEQ / 128, BHN), 256>>>();

    tc_gemm_kernel<<<gg, 256>>>(wt_base + 3 * WSZ, bo, (float*)d_out, 3, 1.0f);
}

// round 6
// speedup vs baseline: 3.3879x; 1.1311x over previous
#include <cuda_runtime.h>
#include <cuda_fp16.h>
#include <math.h>
#include <stdint.h>

#define D_MODEL 1024
#define NHEAD   16
#define DH      64
#define BATCH   2
#define SEQ     2048
#define MROWS   (BATCH*SEQ)   // 4096
#define BHN     (BATCH*NHEAD) // 32

// Scratch (allocation-free): fp16 buffers.
__device__ __align__(16) __half g_Qh[BHN * SEQ * DH];
__device__ __align__(16) __half g_Kh[BHN * SEQ * DH];
__device__ __align__(16) __half g_Vh[BHN * SEQ * DH];
__device__ __align__(16) __half g_Oh[BHN * SEQ * DH];
__device__ __align__(16) __half g_xh[MROWS * D_MODEL];
__device__ __align__(16) __half g_Wt[4][D_MODEL * D_MODEL];  // [n][k] fp16

// ---------------------------------------------------------------------------
// helpers
// ---------------------------------------------------------------------------
__device__ __forceinline__ uint32_t pack2(float a, float b) {
    __half2 h = __floats2half2_rn(a, b);
    return *reinterpret_cast<uint32_t*>(&h);
}
__device__ __forceinline__ uint32_t smem_u32(const void* p) {
    uint32_t r;
    asm("{ .reg .u64 t; cvta.to.shared.u64 t, %1; cvt.u32.u64 %0, t; }"
        : "=r"(r) : "l"(p));
    return r;
}
__device__ __forceinline__ void mma16(float* c, const uint32_t* a,
                                      uint32_t b0, uint32_t b1) {
    asm volatile(
        "mma.sync.aligned.m16n8k16.row.col.f32.f16.f16.f32 "
        "{%0,%1,%2,%3}, {%4,%5,%6,%7}, {%8,%9}, {%0,%1,%2,%3};"
        : "+f"(c[0]), "+f"(c[1]), "+f"(c[2]), "+f"(c[3])
        : "r"(a[0]), "r"(a[1]), "r"(a[2]), "r"(a[3]), "r"(b0), "r"(b1));
}
__device__ __forceinline__ void ldm_x4(uint32_t* r, uint32_t addr) {
    asm volatile("ldmatrix.sync.aligned.m8n8.x4.shared.b16 {%0,%1,%2,%3}, [%4];"
        : "=r"(r[0]), "=r"(r[1]), "=r"(r[2]), "=r"(r[3]) : "r"(addr));
}
__device__ __forceinline__ void ldm_x4_t(uint32_t* r, uint32_t addr) {
    asm volatile("ldmatrix.sync.aligned.m8n8.x4.trans.shared.b16 {%0,%1,%2,%3}, [%4];"
        : "=r"(r[0]), "=r"(r[1]), "=r"(r[2]), "=r"(r[3]) : "r"(addr));
}
__device__ __forceinline__ void cpa16(uint32_t dst, const void* src) {
    asm volatile("cp.async.cg.shared.global [%0], [%1], 16;"
                 :: "r"(dst), "l"(src) : "memory");
}
#define CPA_COMMIT() asm volatile("cp.async.commit_group;" ::: "memory")
#define CPA_WAIT0()  asm volatile("cp.async.wait_group 0;" ::: "memory")

// ---------------------------------------------------------------------------
// Pre-pass: x (f32) -> g_xh (f16)
// ---------------------------------------------------------------------------
__global__ __launch_bounds__(256) void conv_x_kernel(const float* __restrict__ x)
{
    int idx = blockIdx.x * 256 + threadIdx.x;
    float4 v = *(const float4*)(x + (size_t)idx * 4);
    uint2 u = make_uint2(pack2(v.x, v.y), pack2(v.z, v.w));
    *(uint2*)(g_xh + (size_t)idx * 4) = u;
}

// ---------------------------------------------------------------------------
// Pre-pass: all 4 weights [k][n] f32 -> g_Wt[z] [n][k] f16. 32x32 tiles.
// ---------------------------------------------------------------------------
__global__ __launch_bounds__(256) void transpose_w_kernel(
    const float* __restrict__ W0, const float* __restrict__ W1,
    const float* __restrict__ W2, const float* __restrict__ W3)
{
    __shared__ float tile[32][33];
    const int z = blockIdx.z;
    const float* W = (z == 0) ? W0 : (z == 1) ? W1 : (z == 2) ? W2 : W3;
    const int tx = threadIdx.x & 31, ty = threadIdx.x >> 5;  // (32, 8)
    const int k0 = blockIdx.y * 32, n0 = blockIdx.x * 32;
    #pragma unroll
    for (int j = 0; j < 4; j++)
        tile[ty + 8 * j][tx] = W[(size_t)(k0 + ty + 8 * j) * D_MODEL + n0 + tx];
    __syncthreads();
    __half* Wt = g_Wt[z];
    #pragma unroll
    for (int jj = 0; jj < 2; jj++) {
        int w_ = threadIdx.x + 256 * jj;   // 0..511
        int n = w_ >> 4, c = w_ & 15;
        uint32_t u = pack2(tile[2 * c][n], tile[2 * c + 1][n]);
        *(uint32_t*)(Wt + (size_t)(n0 + n) * D_MODEL + k0 + 2 * c) = u;
    }
}

// ---------------------------------------------------------------------------
// Shared GEMM geometry
// ---------------------------------------------------------------------------
#define BK   32
#define NS   (D_MODEL / BK)        // 32
#define GST  20                     // u32 words per smem row
#define BUFW (256 * GST)            // A(128 rows) + W(128 rows) per buffer

// compute one BK stage's MMAs given smem buffer base address
struct GemmCtx {
    int m0w, n0w;
    int lrow, a_roff, a_coff, b_roff, b_coff;
};
__device__ __forceinline__ void gemm_stage(const GemmCtx& c, uint32_t ab,
                                           float acc[4][4][4]) {
    const uint32_t wb = ab + 128 * GST * 4;
    #pragma unroll
    for (int ks = 0; ks < 2; ks++) {
        const int k0w = ks * 8;
        uint32_t a[4][4], b[2][4];
        #pragma unroll
        for (int mt = 0; mt < 4; mt++)
            ldm_x4(a[mt], ab + ((c.m0w + mt * 16 + c.a_roff + c.lrow) * GST
                                + k0w + c.a_coff) * 4);
        #pragma unroll
        for (int np = 0; np < 2; np++)
            ldm_x4(b[np], wb + ((c.n0w + np * 16 + c.b_roff + c.lrow) * GST
                                + k0w + c.b_coff) * 4);
        #pragma unroll
        for (int nt = 0; nt < 4; nt++) {
            uint32_t b0 = b[nt >> 1][(nt & 1) * 2];
            uint32_t b1 = b[nt >> 1][(nt & 1) * 2 + 1];
            #pragma unroll
            for (int mt = 0; mt < 4; mt++)
                mma16(acc[mt][nt], a[mt], b0, b1);
        }
    }
}

// ---------------------------------------------------------------------------
// Fused QKV projection GEMM. grid (8, 32, 3): z selects W/bias/output.
// cp.async double-buffered, one sync per stage.
// ---------------------------------------------------------------------------
__global__ __launch_bounds__(256, 2) void qkv_gemm_kernel(
    const __half* __restrict__ wt_base,
    const float* __restrict__ bq, const float* __restrict__ bk,
    const float* __restrict__ bv)
{
    __shared__ uint32_t sm[2 * BUFW];   // 40 KB

    const int tid  = threadIdx.x;
    const int w    = tid >> 5, lane = tid & 31;
    const int g    = lane >> 2, t = lane & 3;
    const int wm   = w >> 2, wn = w & 3;
    const int bm   = blockIdx.y * 128, bn = blockIdx.x * 128;
    const int bb   = bm >> 11;
    const int z    = blockIdx.z;

    const __half* Wt = wt_base + (size_t)z * D_MODEL * D_MODEL;
    const float* bias = (z == 0) ? bq : (z == 1) ? bk : bv;
    const float alpha = (z == 0) ? 0.125f : 1.0f;

    GemmCtx c;
    c.m0w = wm * 64; c.n0w = wn * 32;
    c.lrow = lane & 7;
    c.a_roff = ((lane >> 3) & 1) * 8;
    c.a_coff = (lane >> 4) * 4;
    c.b_roff = (lane >> 4) * 8;
    c.b_coff = ((lane >> 3) & 1) * 4;

    const uint32_t smb = smem_u32(sm);
    const int row = tid >> 2, seg = tid & 3;            // i=0 slice
    const int row2 = (tid + 256) >> 2, seg2 = tid & 3;  // i=1 slice

    auto issue = [&](int kt, int buf) {
        uint32_t dst = smb + buf * (BUFW * 4);
        cpa16(dst + (row * GST + seg * 4) * 4,
              g_xh + (size_t)(bm + row) * D_MODEL + kt + seg * 8);
        cpa16(dst + ((128 + row) * GST + seg * 4) * 4,
              Wt + (size_t)(bn + row) * D_MODEL + kt + seg * 8);
        cpa16(dst + (row2 * GST + seg2 * 4) * 4,
              g_xh + (size_t)(bm + row2) * D_MODEL + kt + seg2 * 8);
        cpa16(dst + ((128 + row2) * GST + seg2 * 4) * 4,
              Wt + (size_t)(bn + row2) * D_MODEL + kt + seg2 * 8);
        CPA_COMMIT();
    };

    issue(0, 0);

    float acc[4][4][4] = {};

    #pragma unroll 1
    for (int s = 0; s < NS; s++) {
        const int buf = s & 1;
        CPA_WAIT0();
        __syncthreads();
        if (s + 1 < NS) issue((s + 1) * BK, buf ^ 1);
        gemm_stage(c, smb + buf * (BUFW * 4), acc);
    }

    // Epilogue -> fp16 head-major
    __half* outp = (z == 0) ? g_Qh : (z == 1) ? g_Kh : g_Vh;
    #pragma unroll
    for (int mt = 0; mt < 4; mt++) {
        #pragma unroll
        for (int nt = 0; nt < 4; nt++) {
            int rl = c.m0w + mt * 16 + g;
            int cl = c.n0w + nt * 8 + t * 2;
            float2 bv2 = *(const float2*)&bias[bn + cl];
            float v00 = (acc[mt][nt][0] + bv2.x) * alpha;
            float v01 = (acc[mt][nt][1] + bv2.y) * alpha;
            float v10 = (acc[mt][nt][2] + bv2.x) * alpha;
            float v11 = (acc[mt][nt][3] + bv2.y) * alpha;
            int col = bn + cl;
            int h = col >> 6, d = col & 63;
            int t0r = (bm + rl) & (SEQ - 1);
            __half* ob = outp + ((size_t)(bb * NHEAD + h)) * SEQ * DH;
            *(uint32_t*)&ob[(size_t)t0r * DH + d] = pack2(v00, v01);
            *(uint32_t*)&ob[(size_t)(t0r + 8) * DH + d] = pack2(v10, v11);
        }
    }
}

// ---------------------------------------------------------------------------
// Output GEMM: d_out = concat(O) @ Wo + bo. A gathered from g_Oh head-major.
// ---------------------------------------------------------------------------
__global__ __launch_bounds__(256, 2) void out_gemm_kernel(
    const __half* __restrict__ Wt, const float* __restrict__ bias,
    float* __restrict__ Cout)
{
    __shared__ uint32_t sm[2 * BUFW];

    const int tid  = threadIdx.x;
    const int w    = tid >> 5, lane = tid & 31;
    const int g    = lane >> 2, t = lane & 3;
    const int wm   = w >> 2, wn = w & 3;
    const int bm   = blockIdx.y * 128, bn = blockIdx.x * 128;
    const int bb   = bm >> 11;

    GemmCtx c;
    c.m0w = wm * 64; c.n0w = wn * 32;
    c.lrow = lane & 7;
    c.a_roff = ((lane >> 3) & 1) * 8;
    c.a_coff = (lane >> 4) * 4;
    c.b_roff = (lane >> 4) * 8;
    c.b_coff = ((lane >> 3) & 1) * 4;

    const uint32_t smb = smem_u32(sm);

    auto issue = [&](int kt, int buf) {
        uint32_t dst = smb + buf * (BUFW * 4);
        const int h = kt >> 6, d0 = kt & 63;
        #pragma unroll
        for (int i = 0; i < 2; i++) {
            int idx = tid + 256 * i;
            int row = idx >> 2, seg = idx & 3;
            int tt = (bm + row) & (SEQ - 1);
            cpa16(dst + (row * GST + seg * 4) * 4,
                  g_Oh + (((size_t)(bb * NHEAD + h)) * SEQ + tt) * DH
                  + d0 + seg * 8);
            cpa16(dst + ((128 + row) * GST + seg * 4) * 4,
                  Wt + (size_t)(bn + row) * D_MODEL + kt + seg * 8);
        }
        CPA_COMMIT();
    };

    issue(0, 0);

    float acc[4][4][4] = {};

    #pragma unroll 1
    for (int s = 0; s < NS; s++) {
        const int buf = s & 1;
        CPA_WAIT0();
        __syncthreads();
        if (s + 1 < NS) issue((s + 1) * BK, buf ^ 1);
        gemm_stage(c, smb + buf * (BUFW * 4), acc);
    }

    #pragma unroll
    for (int mt = 0; mt < 4; mt++) {
        #pragma unroll
        for (int nt = 0; nt < 4; nt++) {
            int rl = c.m0w + mt * 16 + g;
            int cl = c.n0w + nt * 8 + t * 2;
            float2 bv2 = *(const float2*)&bias[bn + cl];
            *(float2*)&Cout[(size_t)(bm + rl) * D_MODEL + bn + cl] =
                make_float2(acc[mt][nt][0] + bv2.x, acc[mt][nt][1] + bv2.y);
            *(float2*)&Cout[(size_t)(bm + rl + 8) * D_MODEL + bn + cl] =
                make_float2(acc[mt][nt][2] + bv2.x, acc[mt][nt][3] + bv2.y);
        }
    }
}

// ---------------------------------------------------------------------------
// Flash attention, fp16 MMA + ldmatrix + cp.async double-buffered KV tiles.
// CTA = 128 queries, 8 warps x 16 rows, 64-key tiles.
// ---------------------------------------------------------------------------
#define FST 36
#define KVW (64 * FST)   // words per K (or V) tile

__global__ __launch_bounds__(256, 2) void flash_kernel()
{
    __shared__ uint32_t Ks[2][KVW];   // 18432 B
    __shared__ uint32_t Vs[2][KVW];   // 18432 B

    const int tid = threadIdx.x;
    const int w = tid >> 5, lane = tid & 31;
    const int g = lane >> 2, t = lane & 3;
    const int bh = blockIdx.y;
    const int q0 = blockIdx.x * 128;

    const __half* Qp = g_Qh + ((size_t)bh * SEQ + q0) * DH;
    const __half* Kp = g_Kh + (size_t)bh * SEQ * DH;
    const __half* Vp = g_Vh + (size_t)bh * SEQ * DH;

    const int lr = w * 16 + g;

    // Q fragments in registers (scale folded into projection).
    uint32_t qf[4][4];
    #pragma unroll
    for (int s = 0; s < 4; s++) {
        qf[s][0] = *(const uint32_t*)(Qp + (size_t)lr * DH + s * 16 + 2 * t);
        qf[s][1] = *(const uint32_t*)(Qp + (size_t)(lr + 8) * DH + s * 16 + 2 * t);
        qf[s][2] = *(const uint32_t*)(Qp + (size_t)lr * DH + s * 16 + 8 + 2 * t);
        qf[s][3] = *(const uint32_t*)(Qp + (size_t)(lr + 8) * DH + s * 16 + 8 + 2 * t);
    }

    const uint32_t ksb = smem_u32(Ks), vsb = smem_u32(Vs);
    const int lrow = lane & 7;
    const uint32_t k_lane = ksb + (lrow * FST + (lane >> 3) * 4) * 4;
    const uint32_t v_lane = vsb + ((((lane >> 3) & 1) * 8 + lrow) * FST
                                   + (lane >> 4) * 4) * 4;

    const int krow = tid >> 3, kseg = tid & 7;            // i=0 slice
    const int krow2 = (tid + 256) >> 3;                    // i=1 slice

    auto issueKV = [&](int kt, int buf) {
        const uint32_t koff = buf * (KVW * 4);
        cpa16(ksb + koff + (krow * FST + kseg * 4) * 4,
              Kp + (size_t)(kt + krow) * DH + kseg * 8);
        cpa16(vsb + koff + (krow * FST + kseg * 4) * 4,
              Vp + (size_t)(kt + krow) * DH + kseg * 8);
        cpa16(ksb + koff + (krow2 * FST + kseg * 4) * 4,
              Kp + (size_t)(kt + krow2) * DH + kseg * 8);
        cpa16(vsb + koff + (krow2 * FST + kseg * 4) * 4,
              Vp + (size_t)(kt + krow2) * DH + kseg * 8);
        CPA_COMMIT();
    };

    issueKV(0, 0);

    float o[8][4] = {};
    float m0 = -INFINITY, m1 = -INFINITY, l0 = 0.f, l1 = 0.f;

    #pragma unroll 1
    for (int it = 0; it < SEQ / 64; it++) {
        const int buf = it & 1;
        CPA_WAIT0();
        __syncthreads();
        if (it + 1 < SEQ / 64) issueKV((it + 1) * 64, buf ^ 1);

        const uint32_t kl = k_lane + buf * (KVW * 4);
        const uint32_t vl = v_lane + buf * (KVW * 4);

        // S = Q @ K^T
        float s_[8][4] = {};
        #pragma unroll
        for (int nt = 0; nt < 8; nt++) {
            uint32_t kb[4], kb2[4];
            uint32_t base = kl + nt * 8 * (FST * 4);
            ldm_x4(kb,  base);
            ldm_x4(kb2, base + 16 * 4);
            mma16(s_[nt], qf[0], kb[0],  kb[1]);
            mma16(s_[nt], qf[1], kb[2],  kb[3]);
            mma16(s_[nt], qf[2], kb2[0], kb2[1]);
            mma16(s_[nt], qf[3], kb2[2], kb2[3]);
        }

        // online softmax
        float mx0 = -INFINITY, mx1 = -INFINITY;
        #pragma unroll
        for (int nt = 0; nt < 8; nt++) {
            mx0 = fmaxf(mx0, fmaxf(s_[nt][0], s_[nt][1]));
            mx1 = fmaxf(mx1, fmaxf(s_[nt][2], s_[nt][3]));
        }
        mx0 = fmaxf(mx0, __shfl_xor_sync(0xffffffffu, mx0, 1));
        mx0 = fmaxf(mx0, __shfl_xor_sync(0xffffffffu, mx0, 2));
        mx1 = fmaxf(mx1, __shfl_xor_sync(0xffffffffu, mx1, 1));
        mx1 = fmaxf(mx1, __shfl_xor_sync(0xffffffffu, mx1, 2));

        float mn0 = fmaxf(m0, mx0), mn1 = fmaxf(m1, mx1);
        float c0 = __expf(m0 - mn0), c1 = __expf(m1 - mn1);
        m0 = mn0; m1 = mn1;

        float sum0 = 0.f, sum1 = 0.f;
        #pragma unroll
        for (int nt = 0; nt < 8; nt++) {
            s_[nt][0] = __expf(s_[nt][0] - mn0); sum0 += s_[nt][0];
            s_[nt][1] = __expf(s_[nt][1] - mn0); sum0 += s_[nt][1];
            s_[nt][2] = __expf(s_[nt][2] - mn1); sum1 += s_[nt][2];
            s_[nt][3] = __expf(s_[nt][3] - mn1); sum1 += s_[nt][3];
        }
        sum0 += __shfl_xor_sync(0xffffffffu, sum0, 1);
        sum0 += __shfl_xor_sync(0xffffffffu, sum0, 2);
        sum1 += __shfl_xor_sync(0xffffffffu, sum1, 1);
        sum1 += __shfl_xor_sync(0xffffffffu, sum1, 2);
        l0 = l0 * c0 + sum0;
        l1 = l1 * c1 + sum1;

        #pragma unroll
        for (int nt = 0; nt < 8; nt++) {
            o[nt][0] *= c0; o[nt][1] *= c0;
            o[nt][2] *= c1; o[nt][3] *= c1;
        }

        // P frags in registers
        uint32_t pf[4][4];
        #pragma unroll
        for (int s = 0; s < 4; s++) {
            pf[s][0] = pack2(s_[2 * s][0],     s_[2 * s][1]);
            pf[s][1] = pack2(s_[2 * s][2],     s_[2 * s][3]);
            pf[s][2] = pack2(s_[2 * s + 1][0], s_[2 * s + 1][1]);
            pf[s][3] = pack2(s_[2 * s + 1][2], s_[2 * s + 1][3]);
        }

        // O += P @ V
        #pragma unroll
        for (int s = 0; s < 4; s++) {
            uint32_t base = vl + s * 16 * (FST * 4);
            #pragma unroll
            for (int np = 0; np < 4; np++) {
                uint32_t vb[4];
                ldm_x4_t(vb, base + np * 8 * 4);
                mma16(o[2 * np],     pf[s], vb[0], vb[1]);
                mma16(o[2 * np + 1], pf[s], vb[2], vb[3]);
            }
        }
    }

    // epilogue -> g_Oh
    float inv0 = 1.0f / l0, inv1 = 1.0f / l1;
    __half* Op = g_Oh + ((size_t)bh * SEQ + q0) * DH;
    #pragma unroll
    for (int nt = 0; nt < 8; nt++) {
        int col = nt * 8 + t * 2;
        *(uint32_t*)&Op[(size_t)lr * DH + col] =
            pack2(o[nt][0] * inv0, o[nt][1] * inv0);
        *(uint32_t*)&Op[(size_t)(lr + 8) * DH + col] =
            pack2(o[nt][2] * inv1, o[nt][3] * inv1);
    }
}

// ---------------------------------------------------------------------------
extern "C" void kernel_launch(void* const* d_in, const int* in_sizes, int n_in,
                              void* d_out, int out_size)
{
    const float* x  = (const float*)d_in[0];
    const float* Wq = (const float*)d_in[1];
    const float* bq = (const float*)d_in[2];
    const float* Wk = (const float*)d_in[3];
    const float* bk = (const float*)d_in[4];
    const float* Wv = (const float*)d_in[5];
    const float* bv = (const float*)d_in[6];
    const float* Wo = (const float*)d_in[7];
    const float* bo = (const float*)d_in[8];
    (void)in_sizes; (void)n_in; (void)out_size;

    static __half* wt_base = nullptr;
    if (!wt_base) {
        void* p = nullptr;
        cudaGetSymbolAddress(&p, g_Wt);
        wt_base = (__half*)p;
    }
    const size_t WSZ = (size_t)D_MODEL * D_MODEL;

    conv_x_kernel<<<MROWS * D_MODEL / 1024, 256>>>(x);
    transpose_w_kernel<<<dim3(D_MODEL / 32, D_MODEL / 32, 4), 256>>>(
        Wq, Wk, Wv, Wo);

    qkv_gemm_kernel<<<dim3(D_MODEL / 128, MROWS / 128, 3), 256>>>(
        wt_base, bq, bk, bv);

    flash_kernel<<<dim3(SEQ / 128, BHN), 256>>>();

    out_gemm_kernel<<<dim3(D_MODEL / 128, MROWS / 128), 256>>>(
        wt_base + 3 * WSZ, bo, (float*)d_out);
}

// round 7
// speedup vs baseline: 3.7138x; 1.0962x over previous
#include <cuda_runtime.h>
#include <cuda_fp16.h>
#include <math.h>
#include <stdint.h>

#define D_MODEL 1024
#define NHEAD   16
#define DH      64
#define BATCH   2
#define SEQ     2048
#define MROWS   (BATCH*SEQ)   // 4096
#define BHN     (BATCH*NHEAD) // 32

// Scratch (allocation-free): fp16 buffers.
__device__ __align__(16) __half g_Qh[BHN * SEQ * DH];
__device__ __align__(16) __half g_Kh[BHN * SEQ * DH];
__device__ __align__(16) __half g_Vh[BHN * SEQ * DH];
__device__ __align__(16) __half g_Oh[BHN * SEQ * DH];
__device__ __align__(16) __half g_xh[MROWS * D_MODEL];
__device__ __align__(16) __half g_Wt[4][D_MODEL * D_MODEL];  // [n][k] fp16

// ---------------------------------------------------------------------------
// helpers
// ---------------------------------------------------------------------------
__device__ __forceinline__ uint32_t pack2(float a, float b) {
    __half2 h = __floats2half2_rn(a, b);
    return *reinterpret_cast<uint32_t*>(&h);
}
__device__ __forceinline__ uint32_t smem_u32(const void* p) {
    uint32_t r;
    asm("{ .reg .u64 t; cvta.to.shared.u64 t, %1; cvt.u32.u64 %0, t; }"
        : "=r"(r) : "l"(p));
    return r;
}
__device__ __forceinline__ void mma16(float* c, const uint32_t* a,
                                      uint32_t b0, uint32_t b1) {
    asm volatile(
        "mma.sync.aligned.m16n8k16.row.col.f32.f16.f16.f32 "
        "{%0,%1,%2,%3}, {%4,%5,%6,%7}, {%8,%9}, {%0,%1,%2,%3};"
        : "+f"(c[0]), "+f"(c[1]), "+f"(c[2]), "+f"(c[3])
        : "r"(a[0]), "r"(a[1]), "r"(a[2]), "r"(a[3]), "r"(b0), "r"(b1));
}
__device__ __forceinline__ void ldm_x4(uint32_t* r, uint32_t addr) {
    asm volatile("ldmatrix.sync.aligned.m8n8.x4.shared.b16 {%0,%1,%2,%3}, [%4];"
        : "=r"(r[0]), "=r"(r[1]), "=r"(r[2]), "=r"(r[3]) : "r"(addr));
}
__device__ __forceinline__ void ldm_x4_t(uint32_t* r, uint32_t addr) {
    asm volatile("ldmatrix.sync.aligned.m8n8.x4.trans.shared.b16 {%0,%1,%2,%3}, [%4];"
        : "=r"(r[0]), "=r"(r[1]), "=r"(r[2]), "=r"(r[3]) : "r"(addr));
}
__device__ __forceinline__ void cpa16(uint32_t dst, const void* src) {
    asm volatile("cp.async.cg.shared.global [%0], [%1], 16;"
                 :: "r"(dst), "l"(src) : "memory");
}
#define CPA_COMMIT() asm volatile("cp.async.commit_group;" ::: "memory")
#define CPA_WAIT0()  asm volatile("cp.async.wait_group 0;" ::: "memory")
#define CPA_WAIT1()  asm volatile("cp.async.wait_group 1;" ::: "memory")

// ---------------------------------------------------------------------------
// Pre-pass: x (f32) -> g_xh (f16)
// ---------------------------------------------------------------------------
__global__ __launch_bounds__(256) void conv_x_kernel(const float* __restrict__ x)
{
    int idx = blockIdx.x * 256 + threadIdx.x;
    float4 v = *(const float4*)(x + (size_t)idx * 4);
    uint2 u = make_uint2(pack2(v.x, v.y), pack2(v.z, v.w));
    *(uint2*)(g_xh + (size_t)idx * 4) = u;
}

// ---------------------------------------------------------------------------
// Pre-pass: all 4 weights [k][n] f32 -> g_Wt[z] [n][k] f16. 32x32 tiles.
// ---------------------------------------------------------------------------
__global__ __launch_bounds__(256) void transpose_w_kernel(
    const float* __restrict__ W0, const float* __restrict__ W1,
    const float* __restrict__ W2, const float* __restrict__ W3)
{
    __shared__ float tile[32][33];
    const int z = blockIdx.z;
    const float* W = (z == 0) ? W0 : (z == 1) ? W1 : (z == 2) ? W2 : W3;
    const int tx = threadIdx.x & 31, ty = threadIdx.x >> 5;  // (32, 8)
    const int k0 = blockIdx.y * 32, n0 = blockIdx.x * 32;
    #pragma unroll
    for (int j = 0; j < 4; j++)
        tile[ty + 8 * j][tx] = W[(size_t)(k0 + ty + 8 * j) * D_MODEL + n0 + tx];
    __syncthreads();
    __half* Wt = g_Wt[z];
    #pragma unroll
    for (int jj = 0; jj < 2; jj++) {
        int w_ = threadIdx.x + 256 * jj;   // 0..511
        int n = w_ >> 4, c = w_ & 15;
        uint32_t u = pack2(tile[2 * c][n], tile[2 * c + 1][n]);
        *(uint32_t*)(Wt + (size_t)(n0 + n) * D_MODEL + k0 + 2 * c) = u;
    }
}

// ---------------------------------------------------------------------------
// Shared GEMM geometry. 3-stage cp.async pipeline (prefetch distance 2).
// ---------------------------------------------------------------------------
#define BK   32
#define NS   (D_MODEL / BK)        // 32
#define GST  20                     // u32 words per smem row
#define BUFW (256 * GST)            // A(128) + W(128) rows per buffer
#define GEMM_SMEM (3 * BUFW * 4)    // 61440 B dynamic

struct GemmCtx {
    int m0w, n0w;
    int lrow, a_roff, a_coff, b_roff, b_coff;
};
__device__ __forceinline__ void gemm_stage(const GemmCtx& c, uint32_t ab,
                                           float acc[4][4][4]) {
    const uint32_t wb = ab + 128 * GST * 4;
    #pragma unroll
    for (int ks = 0; ks < 2; ks++) {
        const int k0w = ks * 8;
        uint32_t a[4][4], b[2][4];
        #pragma unroll
        for (int mt = 0; mt < 4; mt++)
            ldm_x4(a[mt], ab + ((c.m0w + mt * 16 + c.a_roff + c.lrow) * GST
                                + k0w + c.a_coff) * 4);
        #pragma unroll
        for (int np = 0; np < 2; np++)
            ldm_x4(b[np], wb + ((c.n0w + np * 16 + c.b_roff + c.lrow) * GST
                                + k0w + c.b_coff) * 4);
        #pragma unroll
        for (int nt = 0; nt < 4; nt++) {
            uint32_t b0 = b[nt >> 1][(nt & 1) * 2];
            uint32_t b1 = b[nt >> 1][(nt & 1) * 2 + 1];
            #pragma unroll
            for (int mt = 0; mt < 4; mt++)
                mma16(acc[mt][nt], a[mt], b0, b1);
        }
    }
}

// ---------------------------------------------------------------------------
// Fused QKV projection GEMM. grid (8, 32, 3).
// ---------------------------------------------------------------------------
__global__ __launch_bounds__(256, 2) void qkv_gemm_kernel(
    const __half* __restrict__ wt_base,
    const float* __restrict__ bq, const float* __restrict__ bk,
    const float* __restrict__ bv)
{
    extern __shared__ uint32_t sm[];

    const int tid  = threadIdx.x;
    const int w    = tid >> 5, lane = tid & 31;
    const int g    = lane >> 2, t = lane & 3;
    const int wm   = w >> 2, wn = w & 3;
    const int bm   = blockIdx.y * 128, bn = blockIdx.x * 128;
    const int bb   = bm >> 11;
    const int z    = blockIdx.z;

    const __half* Wt = wt_base + (size_t)z * D_MODEL * D_MODEL;
    const float* bias = (z == 0) ? bq : (z == 1) ? bk : bv;
    // Q scale: 1/sqrt(64) * log2(e) for exp2-domain softmax
    const float alpha = (z == 0) ? 0.125f * 1.4426950408889634f : 1.0f;

    GemmCtx c;
    c.m0w = wm * 64; c.n0w = wn * 32;
    c.lrow = lane & 7;
    c.a_roff = ((lane >> 3) & 1) * 8;
    c.a_coff = (lane >> 4) * 4;
    c.b_roff = (lane >> 4) * 8;
    c.b_coff = ((lane >> 3) & 1) * 4;

    const uint32_t smb = smem_u32(sm);
    const int row = tid >> 2, seg = tid & 3;
    const int row2 = (tid + 256) >> 2;

    auto issue = [&](int kt, int buf) {
        uint32_t dst = smb + buf * (BUFW * 4);
        cpa16(dst + (row * GST + seg * 4) * 4,
              g_xh + (size_t)(bm + row) * D_MODEL + kt + seg * 8);
        cpa16(dst + ((128 + row) * GST + seg * 4) * 4,
              Wt + (size_t)(bn + row) * D_MODEL + kt + seg * 8);
        cpa16(dst + (row2 * GST + seg * 4) * 4,
              g_xh + (size_t)(bm + row2) * D_MODEL + kt + seg * 8);
        cpa16(dst + ((128 + row2) * GST + seg * 4) * 4,
              Wt + (size_t)(bn + row2) * D_MODEL + kt + seg * 8);
        CPA_COMMIT();
    };

    issue(0, 0);
    issue(BK, 1);

    float acc[4][4][4] = {};

    #pragma unroll 1
    for (int s = 0; s < NS; s++) {
        if (s + 1 < NS) CPA_WAIT1(); else CPA_WAIT0();
        __syncthreads();
        if (s + 2 < NS) issue((s + 2) * BK, (s + 2) % 3);
        gemm_stage(c, smb + (s % 3) * (BUFW * 4), acc);
    }

    __half* outp = (z == 0) ? g_Qh : (z == 1) ? g_Kh : g_Vh;
    #pragma unroll
    for (int mt = 0; mt < 4; mt++) {
        #pragma unroll
        for (int nt = 0; nt < 4; nt++) {
            int rl = c.m0w + mt * 16 + g;
            int cl = c.n0w + nt * 8 + t * 2;
            float2 bv2 = *(const float2*)&bias[bn + cl];
            float v00 = (acc[mt][nt][0] + bv2.x) * alpha;
            float v01 = (acc[mt][nt][1] + bv2.y) * alpha;
            float v10 = (acc[mt][nt][2] + bv2.x) * alpha;
            float v11 = (acc[mt][nt][3] + bv2.y) * alpha;
            int col = bn + cl;
            int h = col >> 6, d = col & 63;
            int t0r = (bm + rl) & (SEQ - 1);
            __half* ob = outp + ((size_t)(bb * NHEAD + h)) * SEQ * DH;
            *(uint32_t*)&ob[(size_t)t0r * DH + d] = pack2(v00, v01);
            *(uint32_t*)&ob[(size_t)(t0r + 8) * DH + d] = pack2(v10, v11);
        }
    }
}

// ---------------------------------------------------------------------------
// Output GEMM: d_out = concat(O) @ Wo + bo.
// ---------------------------------------------------------------------------
__global__ __launch_bounds__(256, 2) void out_gemm_kernel(
    const __half* __restrict__ Wt, const float* __restrict__ bias,
    float* __restrict__ Cout)
{
    extern __shared__ uint32_t sm[];

    const int tid  = threadIdx.x;
    const int w    = tid >> 5, lane = tid & 31;
    const int g    = lane >> 2, t = lane & 3;
    const int wm   = w >> 2, wn = w & 3;
    const int bm   = blockIdx.y * 128, bn = blockIdx.x * 128;
    const int bb   = bm >> 11;

    GemmCtx c;
    c.m0w = wm * 64; c.n0w = wn * 32;
    c.lrow = lane & 7;
    c.a_roff = ((lane >> 3) & 1) * 8;
    c.a_coff = (lane >> 4) * 4;
    c.b_roff = (lane >> 4) * 8;
    c.b_coff = ((lane >> 3) & 1) * 4;

    const uint32_t smb = smem_u32(sm);

    auto issue = [&](int kt, int buf) {
        uint32_t dst = smb + buf * (BUFW * 4);
        const int h = kt >> 6, d0 = kt & 63;
        #pragma unroll
        for (int i = 0; i < 2; i++) {
            int idx = tid + 256 * i;
            int row = idx >> 2, seg = idx & 3;
            int tt = (bm + row) & (SEQ - 1);
            cpa16(dst + (row * GST + seg * 4) * 4,
                  g_Oh + (((size_t)(bb * NHEAD + h)) * SEQ + tt) * DH
                  + d0 + seg * 8);
            cpa16(dst + ((128 + row) * GST + seg * 4) * 4,
                  Wt + (size_t)(bn + row) * D_MODEL + kt + seg * 8);
        }
        CPA_COMMIT();
    };

    issue(0, 0);
    issue(BK, 1);

    float acc[4][4][4] = {};

    #pragma unroll 1
    for (int s = 0; s < NS; s++) {
        if (s + 1 < NS) CPA_WAIT1(); else CPA_WAIT0();
        __syncthreads();
        if (s + 2 < NS) issue((s + 2) * BK, (s + 2) % 3);
        gemm_stage(c, smb + (s % 3) * (BUFW * 4), acc);
    }

    #pragma unroll
    for (int mt = 0; mt < 4; mt++) {
        #pragma unroll
        for (int nt = 0; nt < 4; nt++) {
            int rl = c.m0w + mt * 16 + g;
            int cl = c.n0w + nt * 8 + t * 2;
            float2 bv2 = *(const float2*)&bias[bn + cl];
            *(float2*)&Cout[(size_t)(bm + rl) * D_MODEL + bn + cl] =
                make_float2(acc[mt][nt][0] + bv2.x, acc[mt][nt][1] + bv2.y);
            *(float2*)&Cout[(size_t)(bm + rl + 8) * D_MODEL + bn + cl] =
                make_float2(acc[mt][nt][2] + bv2.x, acc[mt][nt][3] + bv2.y);
        }
    }
}

// ---------------------------------------------------------------------------
// Flash attention. CTA = 128 threads (4 warps) x 64 queries; 4 CTAs/SM.
// fp16 MMA + ldmatrix + cp.async double-buffered 64-key KV tiles.
// Softmax in exp2 domain (log2e folded into Q projection).
// ---------------------------------------------------------------------------
#define FST 36
#define KVW (64 * FST)   // words per K (or V) tile

__global__ __launch_bounds__(128, 4) void flash_kernel()
{
    __shared__ uint32_t Ks[2][KVW];   // 18432 B
    __shared__ uint32_t Vs[2][KVW];   // 18432 B

    const int tid = threadIdx.x;
    const int w = tid >> 5, lane = tid & 31;
    const int g = lane >> 2, t = lane & 3;
    const int bh = blockIdx.y;
    const int q0 = blockIdx.x * 64;

    const __half* Qp = g_Qh + ((size_t)bh * SEQ + q0) * DH;
    const __half* Kp = g_Kh + (size_t)bh * SEQ * DH;
    const __half* Vp = g_Vh + (size_t)bh * SEQ * DH;

    const int lr = w * 16 + g;

    // Q fragments in registers (scale incl. log2e folded into projection).
    uint32_t qf[4][4];
    #pragma unroll
    for (int s = 0; s < 4; s++) {
        qf[s][0] = *(const uint32_t*)(Qp + (size_t)lr * DH + s * 16 + 2 * t);
        qf[s][1] = *(const uint32_t*)(Qp + (size_t)(lr + 8) * DH + s * 16 + 2 * t);
        qf[s][2] = *(const uint32_t*)(Qp + (size_t)lr * DH + s * 16 + 8 + 2 * t);
        qf[s][3] = *(const uint32_t*)(Qp + (size_t)(lr + 8) * DH + s * 16 + 8 + 2 * t);
    }

    const uint32_t ksb = smem_u32(Ks), vsb = smem_u32(Vs);
    const int lrow = lane & 7;
    const uint32_t k_lane = ksb + (lrow * FST + (lane >> 3) * 4) * 4;
    const uint32_t v_lane = vsb + ((((lane >> 3) & 1) * 8 + lrow) * FST
                                   + (lane >> 4) * 4) * 4;

    auto issueKV = [&](int kt, int buf) {
        const uint32_t koff = buf * (KVW * 4);
        #pragma unroll
        for (int i = 0; i < 4; i++) {
            int idx = i * 128 + tid;
            int row = idx >> 3, seg = idx & 7;
            cpa16(ksb + koff + (row * FST + seg * 4) * 4,
                  Kp + (size_t)(kt + row) * DH + seg * 8);
            cpa16(vsb + koff + (row * FST + seg * 4) * 4,
                  Vp + (size_t)(kt + row) * DH + seg * 8);
        }
        CPA_COMMIT();
    };

    issueKV(0, 0);

    float o[8][4] = {};
    float m0 = -INFINITY, m1 = -INFINITY, l0 = 0.f, l1 = 0.f;

    #pragma unroll 1
    for (int it = 0; it < SEQ / 64; it++) {
        const int buf = it & 1;
        CPA_WAIT0();
        __syncthreads();
        if (it + 1 < SEQ / 64) issueKV((it + 1) * 64, buf ^ 1);

        const uint32_t kl = k_lane + buf * (KVW * 4);
        const uint32_t vl = v_lane + buf * (KVW * 4);

        // S = Q @ K^T (log2-domain scores)
        float s_[8][4] = {};
        #pragma unroll
        for (int nt = 0; nt < 8; nt++) {
            uint32_t kb[4], kb2[4];
            uint32_t base = kl + nt * 8 * (FST * 4);
            ldm_x4(kb,  base);
            ldm_x4(kb2, base + 16 * 4);
            mma16(s_[nt], qf[0], kb[0],  kb[1]);
            mma16(s_[nt], qf[1], kb[2],  kb[3]);
            mma16(s_[nt], qf[2], kb2[0], kb2[1]);
            mma16(s_[nt], qf[3], kb2[2], kb2[3]);
        }

        // online softmax (exp2 domain)
        float mx0 = -INFINITY, mx1 = -INFINITY;
        #pragma unroll
        for (int nt = 0; nt < 8; nt++) {
            mx0 = fmaxf(mx0, fmaxf(s_[nt][0], s_[nt][1]));
            mx1 = fmaxf(mx1, fmaxf(s_[nt][2], s_[nt][3]));
        }
        mx0 = fmaxf(mx0, __shfl_xor_sync(0xffffffffu, mx0, 1));
        mx0 = fmaxf(mx0, __shfl_xor_sync(0xffffffffu, mx0, 2));
        mx1 = fmaxf(mx1, __shfl_xor_sync(0xffffffffu, mx1, 1));
        mx1 = fmaxf(mx1, __shfl_xor_sync(0xffffffffu, mx1, 2));

        float mn0 = fmaxf(m0, mx0), mn1 = fmaxf(m1, mx1);
        float c0 = exp2f(m0 - mn0), c1 = exp2f(m1 - mn1);
        m0 = mn0; m1 = mn1;

        float sum0 = 0.f, sum1 = 0.f;
        #pragma unroll
        for (int nt = 0; nt < 8; nt++) {
            s_[nt][0] = exp2f(s_[nt][0] - mn0); sum0 += s_[nt][0];
            s_[nt][1] = exp2f(s_[nt][1] - mn0); sum0 += s_[nt][1];
            s_[nt][2] = exp2f(s_[nt][2] - mn1); sum1 += s_[nt][2];
            s_[nt][3] = exp2f(s_[nt][3] - mn1); sum1 += s_[nt][3];
        }
        sum0 += __shfl_xor_sync(0xffffffffu, sum0, 1);
        sum0 += __shfl_xor_sync(0xffffffffu, sum0, 2);
        sum1 += __shfl_xor_sync(0xffffffffu, sum1, 1);
        sum1 += __shfl_xor_sync(0xffffffffu, sum1, 2);
        l0 = l0 * c0 + sum0;
        l1 = l1 * c1 + sum1;

        #pragma unroll
        for (int nt = 0; nt < 8; nt++) {
            o[nt][0] *= c0; o[nt][1] *= c0;
            o[nt][2] *= c1; o[nt][3] *= c1;
        }

        // P frags in registers
        uint32_t pf[4][4];
        #pragma unroll
        for (int s = 0; s < 4; s++) {
            pf[s][0] = pack2(s_[2 * s][0],     s_[2 * s][1]);
            pf[s][1] = pack2(s_[2 * s][2],     s_[2 * s][3]);
            pf[s][2] = pack2(s_[2 * s + 1][0], s_[2 * s + 1][1]);
            pf[s][3] = pack2(s_[2 * s + 1][2], s_[2 * s + 1][3]);
        }

        // O += P @ V
        #pragma unroll
        for (int s = 0; s < 4; s++) {
            uint32_t base = vl + s * 16 * (FST * 4);
            #pragma unroll
            for (int np = 0; np < 4; np++) {
                uint32_t vb[4];
                ldm_x4_t(vb, base + np * 8 * 4);
                mma16(o[2 * np],     pf[s], vb[0], vb[1]);
                mma16(o[2 * np + 1], pf[s], vb[2], vb[3]);
            }
        }
    }

    // epilogue -> g_Oh
    float inv0 = 1.0f / l0, inv1 = 1.0f / l1;
    __half* Op = g_Oh + ((size_t)bh * SEQ + q0) * DH;
    #pragma unroll
    for (int nt = 0; nt < 8; nt++) {
        int col = nt * 8 + t * 2;
        *(uint32_t*)&Op[(size_t)lr * DH + col] =
            pack2(o[nt][0] * inv0, o[nt][1] * inv0);
        *(uint32_t*)&Op[(size_t)(lr + 8) * DH + col] =
            pack2(o[nt][2] * inv1, o[nt][3] * inv1);
    }
}

// ---------------------------------------------------------------------------
extern "C" void kernel_launch(void* const* d_in, const int* in_sizes, int n_in,
                              void* d_out, int out_size)
{
    const float* x  = (const float*)d_in[0];
    const float* Wq = (const float*)d_in[1];
    const float* bq = (const float*)d_in[2];
    const float* Wk = (const float*)d_in[3];
    const float* bk = (const float*)d_in[4];
    const float* Wv = (const float*)d_in[5];
    const float* bv = (const float*)d_in[6];
    const float* Wo = (const float*)d_in[7];
    const float* bo = (const float*)d_in[8];
    (void)in_sizes; (void)n_in; (void)out_size;

    static __half* wt_base = nullptr;
    if (!wt_base) {
        void* p = nullptr;
        cudaGetSymbolAddress(&p, g_Wt);
        wt_base = (__half*)p;
        cudaFuncSetAttribute(qkv_gemm_kernel,
            cudaFuncAttributeMaxDynamicSharedMemorySize, GEMM_SMEM);
        cudaFuncSetAttribute(out_gemm_kernel,
            cudaFuncAttributeMaxDynamicSharedMemorySize, GEMM_SMEM);
    }
    const size_t WSZ = (size_t)D_MODEL * D_MODEL;

    conv_x_kernel<<<MROWS * D_MODEL / 1024, 256>>>(x);
    transpose_w_kernel<<<dim3(D_MODEL / 32, D_MODEL / 32, 4), 256>>>(
        Wq, Wk, Wv, Wo);

    qkv_gemm_kernel<<<dim3(D_MODEL / 128, MROWS / 128, 3), 256, GEMM_SMEM>>>(
        wt_base, bq, bk, bv);

    flash_kernel<<<dim3(SEQ / 64, BHN), 128>>>();

    out_gemm_kernel<<<dim3(D_MODEL / 128, MROWS / 128), 256, GEMM_SMEM>>>(
        wt_base + 3 * WSZ, bo, (float*)d_out);
}

// round 8
// speedup vs baseline: 3.8007x; 1.0234x over previous
#include <cuda_runtime.h>
#include <cuda_fp16.h>
#include <math.h>
#include <stdint.h>

#define D_MODEL 1024
#define NHEAD   16
#define DH      64
#define BATCH   2
#define SEQ     2048
#define MROWS   (BATCH*SEQ)   // 4096
#define BHN     (BATCH*NHEAD) // 32

// Scratch (allocation-free): fp16 buffers.
__device__ __align__(16) __half g_Qh[BHN * SEQ * DH];
__device__ __align__(16) __half g_Kh[BHN * SEQ * DH];
__device__ __align__(16) __half g_Vh[BHN * SEQ * DH];
__device__ __align__(16) __half g_Oh[BHN * SEQ * DH];
__device__ __align__(16) __half g_xh[MROWS * D_MODEL];
__device__ __align__(16) __half g_Wt[4][D_MODEL * D_MODEL];  // [n][k] fp16

// ---------------------------------------------------------------------------
// helpers
// ---------------------------------------------------------------------------
__device__ __forceinline__ uint32_t pack2(float a, float b) {
    __half2 h = __floats2half2_rn(a, b);
    return *reinterpret_cast<uint32_t*>(&h);
}
__device__ __forceinline__ uint32_t smem_u32(const void* p) {
    uint32_t r;
    asm("{ .reg .u64 t; cvta.to.shared.u64 t, %1; cvt.u32.u64 %0, t; }"
        : "=r"(r) : "l"(p));
    return r;
}
__device__ __forceinline__ void mma16(float* c, const uint32_t* a,
                                      uint32_t b0, uint32_t b1) {
    asm volatile(
        "mma.sync.aligned.m16n8k16.row.col.f32.f16.f16.f32 "
        "{%0,%1,%2,%3}, {%4,%5,%6,%7}, {%8,%9}, {%0,%1,%2,%3};"
        : "+f"(c[0]), "+f"(c[1]), "+f"(c[2]), "+f"(c[3])
        : "r"(a[0]), "r"(a[1]), "r"(a[2]), "r"(a[3]), "r"(b0), "r"(b1));
}
__device__ __forceinline__ void ldm_x4(uint32_t* r, uint32_t addr) {
    asm volatile("ldmatrix.sync.aligned.m8n8.x4.shared.b16 {%0,%1,%2,%3}, [%4];"
        : "=r"(r[0]), "=r"(r[1]), "=r"(r[2]), "=r"(r[3]) : "r"(addr));
}
__device__ __forceinline__ void ldm_x4_t(uint32_t* r, uint32_t addr) {
    asm volatile("ldmatrix.sync.aligned.m8n8.x4.trans.shared.b16 {%0,%1,%2,%3}, [%4];"
        : "=r"(r[0]), "=r"(r[1]), "=r"(r[2]), "=r"(r[3]) : "r"(addr));
}
__device__ __forceinline__ void cpa16(uint32_t dst, const void* src) {
    asm volatile("cp.async.cg.shared.global [%0], [%1], 16;"
                 :: "r"(dst), "l"(src) : "memory");
}
#define CPA_COMMIT() asm volatile("cp.async.commit_group;" ::: "memory")
#define CPA_WAIT0()  asm volatile("cp.async.wait_group 0;" ::: "memory")
#define CPA_WAIT1()  asm volatile("cp.async.wait_group 1;" ::: "memory")

// ---------------------------------------------------------------------------
// Pre-pass: x (f32) -> g_xh (f16)
// ---------------------------------------------------------------------------
__global__ __launch_bounds__(256) void conv_x_kernel(const float* __restrict__ x)
{
    int idx = blockIdx.x * 256 + threadIdx.x;
    float4 v = *(const float4*)(x + (size_t)idx * 4);
    uint2 u = make_uint2(pack2(v.x, v.y), pack2(v.z, v.w));
    *(uint2*)(g_xh + (size_t)idx * 4) = u;
}

// ---------------------------------------------------------------------------
// Pre-pass: all 4 weights [k][n] f32 -> g_Wt[z] [n][k] f16. 32x32 tiles.
// ---------------------------------------------------------------------------
__global__ __launch_bounds__(256) void transpose_w_kernel(
    const float* __restrict__ W0, const float* __restrict__ W1,
    const float* __restrict__ W2, const float* __restrict__ W3)
{
    __shared__ float tile[32][33];
    const int z = blockIdx.z;
    const float* W = (z == 0) ? W0 : (z == 1) ? W1 : (z == 2) ? W2 : W3;
    const int tx = threadIdx.x & 31, ty = threadIdx.x >> 5;  // (32, 8)
    const int k0 = blockIdx.y * 32, n0 = blockIdx.x * 32;
    #pragma unroll
    for (int j = 0; j < 4; j++)
        tile[ty + 8 * j][tx] = W[(size_t)(k0 + ty + 8 * j) * D_MODEL + n0 + tx];
    __syncthreads();
    __half* Wt = g_Wt[z];
    #pragma unroll
    for (int jj = 0; jj < 2; jj++) {
        int w_ = threadIdx.x + 256 * jj;   // 0..511
        int n = w_ >> 4, c = w_ & 15;
        uint32_t u = pack2(tile[2 * c][n], tile[2 * c + 1][n]);
        *(uint32_t*)(Wt + (size_t)(n0 + n) * D_MODEL + k0 + 2 * c) = u;
    }
}

// ---------------------------------------------------------------------------
// GEMM geometry: CTA 128x128, 128 threads (4 warps, 2x2), warp tile 64x64.
// BK=32, 3-stage cp.async pipeline.
// ---------------------------------------------------------------------------
#define BK   32
#define NS   (D_MODEL / BK)        // 32
#define GST  20                     // u32 words per smem row
#define BUFW (256 * GST)            // A(128) + W(128) rows per buffer
#define GEMM_SMEM (3 * BUFW * 4)    // 61440 B dynamic

struct GemmCtx {
    int m0w, n0w;
    int lrow, a_roff, a_coff, b_roff, b_coff;
};
__device__ __forceinline__ void gemm_stage(const GemmCtx& c, uint32_t ab,
                                           float acc[4][8][4]) {
    const uint32_t wb = ab + 128 * GST * 4;
    #pragma unroll
    for (int ks = 0; ks < 2; ks++) {
        const int k0w = ks * 8;
        uint32_t a[4][4], b[4][4];
        #pragma unroll
        for (int mt = 0; mt < 4; mt++)
            ldm_x4(a[mt], ab + ((c.m0w + mt * 16 + c.a_roff + c.lrow) * GST
                                + k0w + c.a_coff) * 4);
        #pragma unroll
        for (int np = 0; np < 4; np++)
            ldm_x4(b[np], wb + ((c.n0w + np * 16 + c.b_roff + c.lrow) * GST
                                + k0w + c.b_coff) * 4);
        #pragma unroll
        for (int nt = 0; nt < 8; nt++) {
            uint32_t b0 = b[nt >> 1][(nt & 1) * 2];
            uint32_t b1 = b[nt >> 1][(nt & 1) * 2 + 1];
            #pragma unroll
            for (int mt = 0; mt < 4; mt++)
                mma16(acc[mt][nt], a[mt], b0, b1);
        }
    }
}

// ---------------------------------------------------------------------------
// Fused QKV projection GEMM. grid (8, 32, 3), block 128.
// ---------------------------------------------------------------------------
__global__ __launch_bounds__(128, 2) void qkv_gemm_kernel(
    const __half* __restrict__ wt_base,
    const float* __restrict__ bq, const float* __restrict__ bk,
    const float* __restrict__ bv)
{
    extern __shared__ uint32_t sm[];

    const int tid  = threadIdx.x;
    const int w    = tid >> 5, lane = tid & 31;
    const int g    = lane >> 2, t = lane & 3;
    const int bm   = blockIdx.y * 128, bn = blockIdx.x * 128;
    const int bb   = bm >> 11;
    const int z    = blockIdx.z;

    const __half* Wt = wt_base + (size_t)z * D_MODEL * D_MODEL;
    const float* bias = (z == 0) ? bq : (z == 1) ? bk : bv;
    const float alpha = (z == 0) ? 0.125f * 1.4426950408889634f : 1.0f;

    GemmCtx c;
    c.m0w = (w >> 1) * 64; c.n0w = (w & 1) * 64;
    c.lrow = lane & 7;
    c.a_roff = ((lane >> 3) & 1) * 8;
    c.a_coff = (lane >> 4) * 4;
    c.b_roff = (lane >> 4) * 8;
    c.b_coff = ((lane >> 3) & 1) * 4;

    const uint32_t smb = smem_u32(sm);

    auto issue = [&](int kt, int buf) {
        uint32_t dst = smb + buf * (BUFW * 4);
        #pragma unroll
        for (int i = 0; i < 4; i++) {
            int idx = tid + 128 * i;
            int row = idx >> 2, seg = idx & 3;
            cpa16(dst + (row * GST + seg * 4) * 4,
                  g_xh + (size_t)(bm + row) * D_MODEL + kt + seg * 8);
            cpa16(dst + ((128 + row) * GST + seg * 4) * 4,
                  Wt + (size_t)(bn + row) * D_MODEL + kt + seg * 8);
        }
        CPA_COMMIT();
    };

    issue(0, 0);
    issue(BK, 1);

    float acc[4][8][4] = {};

    #pragma unroll 1
    for (int s = 0; s < NS; s++) {
        if (s + 1 < NS) CPA_WAIT1(); else CPA_WAIT0();
        __syncthreads();
        if (s + 2 < NS) issue((s + 2) * BK, (s + 2) % 3);
        gemm_stage(c, smb + (s % 3) * (BUFW * 4), acc);
    }

    __half* outp = (z == 0) ? g_Qh : (z == 1) ? g_Kh : g_Vh;
    #pragma unroll
    for (int mt = 0; mt < 4; mt++) {
        #pragma unroll
        for (int nt = 0; nt < 8; nt++) {
            int rl = c.m0w + mt * 16 + g;
            int cl = c.n0w + nt * 8 + t * 2;
            float2 bv2 = *(const float2*)&bias[bn + cl];
            float v00 = (acc[mt][nt][0] + bv2.x) * alpha;
            float v01 = (acc[mt][nt][1] + bv2.y) * alpha;
            float v10 = (acc[mt][nt][2] + bv2.x) * alpha;
            float v11 = (acc[mt][nt][3] + bv2.y) * alpha;
            int col = bn + cl;
            int h = col >> 6, d = col & 63;
            int t0r = (bm + rl) & (SEQ - 1);
            __half* ob = outp + ((size_t)(bb * NHEAD + h)) * SEQ * DH;
            *(uint32_t*)&ob[(size_t)t0r * DH + d] = pack2(v00, v01);
            *(uint32_t*)&ob[(size_t)(t0r + 8) * DH + d] = pack2(v10, v11);
        }
    }
}

// ---------------------------------------------------------------------------
// Output GEMM: d_out = concat(O) @ Wo + bo. grid (8, 32), block 128.
// ---------------------------------------------------------------------------
__global__ __launch_bounds__(128, 2) void out_gemm_kernel(
    const __half* __restrict__ Wt, const float* __restrict__ bias,
    float* __restrict__ Cout)
{
    extern __shared__ uint32_t sm[];

    const int tid  = threadIdx.x;
    const int w    = tid >> 5, lane = tid & 31;
    const int g    = lane >> 2, t = lane & 3;
    const int bm   = blockIdx.y * 128, bn = blockIdx.x * 128;
    const int bb   = bm >> 11;

    GemmCtx c;
    c.m0w = (w >> 1) * 64; c.n0w = (w & 1) * 64;
    c.lrow = lane & 7;
    c.a_roff = ((lane >> 3) & 1) * 8;
    c.a_coff = (lane >> 4) * 4;
    c.b_roff = (lane >> 4) * 8;
    c.b_coff = ((lane >> 3) & 1) * 4;

    const uint32_t smb = smem_u32(sm);

    auto issue = [&](int kt, int buf) {
        uint32_t dst = smb + buf * (BUFW * 4);
        const int h = kt >> 6, d0 = kt & 63;
        #pragma unroll
        for (int i = 0; i < 4; i++) {
            int idx = tid + 128 * i;
            int row = idx >> 2, seg = idx & 3;
            int tt = (bm + row) & (SEQ - 1);
            cpa16(dst + (row * GST + seg * 4) * 4,
                  g_Oh + (((size_t)(bb * NHEAD + h)) * SEQ + tt) * DH
                  + d0 + seg * 8);
            cpa16(dst + ((128 + row) * GST + seg * 4) * 4,
                  Wt + (size_t)(bn + row) * D_MODEL + kt + seg * 8);
        }
        CPA_COMMIT();
    };

    issue(0, 0);
    issue(BK, 1);

    float acc[4][8][4] = {};

    #pragma unroll 1
    for (int s = 0; s < NS; s++) {
        if (s + 1 < NS) CPA_WAIT1(); else CPA_WAIT0();
        __syncthreads();
        if (s + 2 < NS) issue((s + 2) * BK, (s + 2) % 3);
        gemm_stage(c, smb + (s % 3) * (BUFW * 4), acc);
    }

    #pragma unroll
    for (int mt = 0; mt < 4; mt++) {
        #pragma unroll
        for (int nt = 0; nt < 8; nt++) {
            int rl = c.m0w + mt * 16 + g;
            int cl = c.n0w + nt * 8 + t * 2;
            float2 bv2 = *(const float2*)&bias[bn + cl];
            *(float2*)&Cout[(size_t)(bm + rl) * D_MODEL + bn + cl] =
                make_float2(acc[mt][nt][0] + bv2.x, acc[mt][nt][1] + bv2.y);
            *(float2*)&Cout[(size_t)(bm + rl + 8) * D_MODEL + bn + cl] =
                make_float2(acc[mt][nt][2] + bv2.x, acc[mt][nt][3] + bv2.y);
        }
    }
}

// ---------------------------------------------------------------------------
// Flash attention, software-pipelined: QK^T(i+1) overlaps softmax(i)/PV(i).
// CTA = 128 threads (4 warps) x 64 queries. K prefetched one tile ahead of V.
// Softmax in exp2 domain.
// ---------------------------------------------------------------------------
#define FST 36
#define KVW (64 * FST)
#define NT  (SEQ / 64)   // 32

__global__ __launch_bounds__(128, 3) void flash_kernel()
{
    __shared__ uint32_t Ks[2][KVW];   // 18432 B
    __shared__ uint32_t Vs[2][KVW];   // 18432 B

    const int tid = threadIdx.x;
    const int w = tid >> 5, lane = tid & 31;
    const int g = lane >> 2, t = lane & 3;
    const int bh = blockIdx.y;
    const int q0 = blockIdx.x * 64;

    const __half* Qp = g_Qh + ((size_t)bh * SEQ + q0) * DH;
    const __half* Kp = g_Kh + (size_t)bh * SEQ * DH;
    const __half* Vp = g_Vh + (size_t)bh * SEQ * DH;

    const int lr = w * 16 + g;

    uint32_t qf[4][4];
    #pragma unroll
    for (int s = 0; s < 4; s++) {
        qf[s][0] = *(const uint32_t*)(Qp + (size_t)lr * DH + s * 16 + 2 * t);
        qf[s][1] = *(const uint32_t*)(Qp + (size_t)(lr + 8) * DH + s * 16 + 2 * t);
        qf[s][2] = *(const uint32_t*)(Qp + (size_t)lr * DH + s * 16 + 8 + 2 * t);
        qf[s][3] = *(const uint32_t*)(Qp + (size_t)(lr + 8) * DH + s * 16 + 8 + 2 * t);
    }

    const uint32_t ksb = smem_u32(Ks), vsb = smem_u32(Vs);
    const int lrow = lane & 7;
    const uint32_t k_lane = ksb + (lrow * FST + (lane >> 3) * 4) * 4;
    const uint32_t v_lane = vsb + ((((lane >> 3) & 1) * 8 + lrow) * FST
                                   + (lane >> 4) * 4) * 4;

    auto issueK = [&](int kt, int buf) {
        const uint32_t koff = buf * (KVW * 4);
        #pragma unroll
        for (int i = 0; i < 4; i++) {
            int idx = i * 128 + tid;
            int row = idx >> 3, seg = idx & 7;
            cpa16(ksb + koff + (row * FST + seg * 4) * 4,
                  Kp + (size_t)(kt + row) * DH + seg * 8);
        }
    };
    auto issueV = [&](int kt, int buf) {
        const uint32_t koff = buf * (KVW * 4);
        #pragma unroll
        for (int i = 0; i < 4; i++) {
            int idx = i * 128 + tid;
            int row = idx >> 3, seg = idx & 7;
            cpa16(vsb + koff + (row * FST + seg * 4) * 4,
                  Vp + (size_t)(kt + row) * DH + seg * 8);
        }
    };

    auto qk = [&](uint32_t kl, float (*s8)[4]) {
        #pragma unroll
        for (int nt = 0; nt < 8; nt++) {
            uint32_t kb[4], kb2[4];
            uint32_t base = kl + nt * 8 * (FST * 4);
            ldm_x4(kb,  base);
            ldm_x4(kb2, base + 16 * 4);
            mma16(s8[nt], qf[0], kb[0],  kb[1]);
            mma16(s8[nt], qf[1], kb[2],  kb[3]);
            mma16(s8[nt], qf[2], kb2[0], kb2[1]);
            mma16(s8[nt], qf[3], kb2[2], kb2[3]);
        }
    };

    // Prologue: K(0) alone; then QK(0); then group0 = {V(0), K(1)}.
    issueK(0, 0); CPA_COMMIT();
    CPA_WAIT0(); __syncthreads();

    float s_[2][8][4];
    #pragma unroll
    for (int nt = 0; nt < 8; nt++)
        #pragma unroll
        for (int j = 0; j < 4; j++) s_[0][nt][j] = 0.f;
    qk(k_lane, s_[0]);

    issueV(0, 0); issueK(64, 1); CPA_COMMIT();

    float o[8][4] = {};
    float m0 = -INFINITY, m1 = -INFINITY, l0 = 0.f, l1 = 0.f;

    #pragma unroll 2
    for (int it = 0; it < NT; it++) {
        const int cur = it & 1, nxt = cur ^ 1;
        CPA_WAIT0();             // V(it) and K(it+1) landed
        __syncthreads();
        if (it + 1 < NT) {
            issueV((it + 1) * 64, nxt);
            if (it + 2 < NT) issueK((it + 2) * 64, cur);
            CPA_COMMIT();
        }

        // row max of s_[cur]
        float mx0 = -INFINITY, mx1 = -INFINITY;
        #pragma unroll
        for (int nt = 0; nt < 8; nt++) {
            mx0 = fmaxf(mx0, fmaxf(s_[cur][nt][0], s_[cur][nt][1]));
            mx1 = fmaxf(mx1, fmaxf(s_[cur][nt][2], s_[cur][nt][3]));
        }
        mx0 = fmaxf(mx0, __shfl_xor_sync(0xffffffffu, mx0, 1));
        mx0 = fmaxf(mx0, __shfl_xor_sync(0xffffffffu, mx0, 2));
        mx1 = fmaxf(mx1, __shfl_xor_sync(0xffffffffu, mx1, 1));
        mx1 = fmaxf(mx1, __shfl_xor_sync(0xffffffffu, mx1, 2));
        float mn0 = fmaxf(m0, mx0), mn1 = fmaxf(m1, mx1);
        float c0 = exp2f(m0 - mn0), c1 = exp2f(m1 - mn1);
        m0 = mn0; m1 = mn1;

        // QK(it+1) on tensor pipe while softmax math below executes
        if (it + 1 < NT) {
            #pragma unroll
            for (int nt = 0; nt < 8; nt++)
                #pragma unroll
                for (int j = 0; j < 4; j++) s_[nxt][nt][j] = 0.f;
            qk(k_lane + nxt * (KVW * 4), s_[nxt]);
        }

        // exp2 + sums + rescale
        float sum0 = 0.f, sum1 = 0.f;
        #pragma unroll
        for (int nt = 0; nt < 8; nt++) {
            s_[cur][nt][0] = exp2f(s_[cur][nt][0] - mn0); sum0 += s_[cur][nt][0];
            s_[cur][nt][1] = exp2f(s_[cur][nt][1] - mn0); sum0 += s_[cur][nt][1];
            s_[cur][nt][2] = exp2f(s_[cur][nt][2] - mn1); sum1 += s_[cur][nt][2];
            s_[cur][nt][3] = exp2f(s_[cur][nt][3] - mn1); sum1 += s_[cur][nt][3];
        }
        sum0 += __shfl_xor_sync(0xffffffffu, sum0, 1);
        sum0 += __shfl_xor_sync(0xffffffffu, sum0, 2);
        sum1 += __shfl_xor_sync(0xffffffffu, sum1, 1);
        sum1 += __shfl_xor_sync(0xffffffffu, sum1, 2);
        l0 = l0 * c0 + sum0;
        l1 = l1 * c1 + sum1;

        #pragma unroll
        for (int nt = 0; nt < 8; nt++) {
            o[nt][0] *= c0; o[nt][1] *= c0;
            o[nt][2] *= c1; o[nt][3] *= c1;
        }

        uint32_t pf[4][4];
        #pragma unroll
        for (int s = 0; s < 4; s++) {
            pf[s][0] = pack2(s_[cur][2 * s][0],     s_[cur][2 * s][1]);
            pf[s][1] = pack2(s_[cur][2 * s][2],     s_[cur][2 * s][3]);
            pf[s][2] = pack2(s_[cur][2 * s + 1][0], s_[cur][2 * s + 1][1]);
            pf[s][3] = pack2(s_[cur][2 * s + 1][2], s_[cur][2 * s + 1][3]);
        }

        // O += P @ V from Vbuf[cur]
        const uint32_t vl = v_lane + cur * (KVW * 4);
        #pragma unroll
        for (int s = 0; s < 4; s++) {
            uint32_t base = vl + s * 16 * (FST * 4);
            #pragma unroll
            for (int np = 0; np < 4; np++) {
                uint32_t vb[4];
                ldm_x4_t(vb, base + np * 8 * 4);
                mma16(o[2 * np],     pf[s], vb[0], vb[1]);
                mma16(o[2 * np + 1], pf[s], vb[2], vb[3]);
            }
        }
    }

    float inv0 = 1.0f / l0, inv1 = 1.0f / l1;
    __half* Op = g_Oh + ((size_t)bh * SEQ + q0) * DH;
    #pragma unroll
    for (int nt = 0; nt < 8; nt++) {
        int col = nt * 8 + t * 2;
        *(uint32_t*)&Op[(size_t)lr * DH + col] =
            pack2(o[nt][0] * inv0, o[nt][1] * inv0);
        *(uint32_t*)&Op[(size_t)(lr + 8) * DH + col] =
            pack2(o[nt][2] * inv1, o[nt][3] * inv1);
    }
}

// ---------------------------------------------------------------------------
extern "C" void kernel_launch(void* const* d_in, const int* in_sizes, int n_in,
                              void* d_out, int out_size)
{
    const float* x  = (const float*)d_in[0];
    const float* Wq = (const float*)d_in[1];
    const float* bq = (const float*)d_in[2];
    const float* Wk = (const float*)d_in[3];
    const float* bk = (const float*)d_in[4];
    const float* Wv = (const float*)d_in[5];
    const float* bv = (const float*)d_in[6];
    const float* Wo = (const float*)d_in[7];
    const float* bo = (const float*)d_in[8];
    (void)in_sizes; (void)n_in; (void)out_size;

    static __half* wt_base = nullptr;
    if (!wt_base) {
        void* p = nullptr;
        cudaGetSymbolAddress(&p, g_Wt);
        wt_base = (__half*)p;
        cudaFuncSetAttribute(qkv_gemm_kernel,
            cudaFuncAttributeMaxDynamicSharedMemorySize, GEMM_SMEM);
        cudaFuncSetAttribute(out_gemm_kernel,
            cudaFuncAttributeMaxDynamicSharedMemorySize, GEMM_SMEM);
    }
    const size_t WSZ = (size_t)D_MODEL * D_MODEL;

    conv_x_kernel<<<MROWS * D_MODEL / 1024, 256>>>(x);
    transpose_w_kernel<<<dim3(D_MODEL / 32, D_MODEL / 32, 4), 256>>>(
        Wq, Wk, Wv, Wo);

    qkv_gemm_kernel<<<dim3(D_MODEL / 128, MROWS / 128, 3), 128, GEMM_SMEM>>>(
        wt_base, bq, bk, bv);

    flash_kernel<<<dim3(SEQ / 64, BHN), 128>>>();

    out_gemm_kernel<<<dim3(D_MODEL / 128, MROWS / 128), 128, GEMM_SMEM>>>(
        wt_base + 3 * WSZ, bo, (float*)d_out);
}

// round 9
// speedup vs baseline: 3.9883x; 1.0494x over previous
#include <cuda_runtime.h>
#include <cuda_fp16.h>
#include <math.h>
#include <stdint.h>

#define D_MODEL 1024
#define NHEAD   16
#define DH      64
#define BATCH   2
#define SEQ     2048
#define MROWS   (BATCH*SEQ)   // 4096
#define BHN     (BATCH*NHEAD) // 32

// Scratch (allocation-free): fp16 buffers.
__device__ __align__(16) __half g_Qh[BHN * SEQ * DH];
__device__ __align__(16) __half g_Kh[BHN * SEQ * DH];
__device__ __align__(16) __half g_Vh[BHN * SEQ * DH];
__device__ __align__(16) __half g_Oh[BHN * SEQ * DH];
__device__ __align__(16) __half g_xh[MROWS * D_MODEL];
__device__ __align__(16) __half g_Wt[4][D_MODEL * D_MODEL];  // [n][k] fp16

// ---------------------------------------------------------------------------
// helpers
// ---------------------------------------------------------------------------
__device__ __forceinline__ uint32_t pack2(float a, float b) {
    __half2 h = __floats2half2_rn(a, b);
    return *reinterpret_cast<uint32_t*>(&h);
}
__device__ __forceinline__ uint32_t smem_u32(const void* p) {
    uint32_t r;
    asm("{ .reg .u64 t; cvta.to.shared.u64 t, %1; cvt.u32.u64 %0, t; }"
        : "=r"(r) : "l"(p));
    return r;
}
__device__ __forceinline__ void mma16(float* c, const uint32_t* a,
                                      uint32_t b0, uint32_t b1) {
    asm volatile(
        "mma.sync.aligned.m16n8k16.row.col.f32.f16.f16.f32 "
        "{%0,%1,%2,%3}, {%4,%5,%6,%7}, {%8,%9}, {%0,%1,%2,%3};"
        : "+f"(c[0]), "+f"(c[1]), "+f"(c[2]), "+f"(c[3])
        : "r"(a[0]), "r"(a[1]), "r"(a[2]), "r"(a[3]), "r"(b0), "r"(b1));
}
__device__ __forceinline__ void ldm_x4(uint32_t* r, uint32_t addr) {
    asm volatile("ldmatrix.sync.aligned.m8n8.x4.shared.b16 {%0,%1,%2,%3}, [%4];"
        : "=r"(r[0]), "=r"(r[1]), "=r"(r[2]), "=r"(r[3]) : "r"(addr));
}
__device__ __forceinline__ void ldm_x4_t(uint32_t* r, uint32_t addr) {
    asm volatile("ldmatrix.sync.aligned.m8n8.x4.trans.shared.b16 {%0,%1,%2,%3}, [%4];"
        : "=r"(r[0]), "=r"(r[1]), "=r"(r[2]), "=r"(r[3]) : "r"(addr));
}
__device__ __forceinline__ void cpa16(uint32_t dst, const void* src) {
    asm volatile("cp.async.cg.shared.global [%0], [%1], 16;"
                 :: "r"(dst), "l"(src) : "memory");
}
#define CPA_COMMIT() asm volatile("cp.async.commit_group;" ::: "memory")
#define CPA_WAIT0()  asm volatile("cp.async.wait_group 0;" ::: "memory")
#define CPA_WAIT1()  asm volatile("cp.async.wait_group 1;" ::: "memory")

// ---------------------------------------------------------------------------
// Pre-pass: x (f32) -> g_xh (f16)
// ---------------------------------------------------------------------------
__global__ __launch_bounds__(256) void conv_x_kernel(const float* __restrict__ x)
{
    int idx = blockIdx.x * 256 + threadIdx.x;
    float4 v = *(const float4*)(x + (size_t)idx * 4);
    uint2 u = make_uint2(pack2(v.x, v.y), pack2(v.z, v.w));
    *(uint2*)(g_xh + (size_t)idx * 4) = u;
}

// ---------------------------------------------------------------------------
// Pre-pass: all 4 weights [k][n] f32 -> g_Wt[z] [n][k] f16. 32x32 tiles.
// ---------------------------------------------------------------------------
__global__ __launch_bounds__(256) void transpose_w_kernel(
    const float* __restrict__ W0, const float* __restrict__ W1,
    const float* __restrict__ W2, const float* __restrict__ W3)
{
    __shared__ float tile[32][33];
    const int z = blockIdx.z;
    const float* W = (z == 0) ? W0 : (z == 1) ? W1 : (z == 2) ? W2 : W3;
    const int tx = threadIdx.x & 31, ty = threadIdx.x >> 5;  // (32, 8)
    const int k0 = blockIdx.y * 32, n0 = blockIdx.x * 32;
    #pragma unroll
    for (int j = 0; j < 4; j++)
        tile[ty + 8 * j][tx] = W[(size_t)(k0 + ty + 8 * j) * D_MODEL + n0 + tx];
    __syncthreads();
    __half* Wt = g_Wt[z];
    #pragma unroll
    for (int jj = 0; jj < 2; jj++) {
        int w_ = threadIdx.x + 256 * jj;   // 0..511
        int n = w_ >> 4, c = w_ & 15;
        uint32_t u = pack2(tile[2 * c][n], tile[2 * c + 1][n]);
        *(uint32_t*)(Wt + (size_t)(n0 + n) * D_MODEL + k0 + 2 * c) = u;
    }
}

// ---------------------------------------------------------------------------
// GEMM geometry: CTA 128x128, 128 threads (4 warps, 2x2), warp tile 64x64.
// BK=32, 3-stage cp.async pipeline. (R8 config — measured good.)
// ---------------------------------------------------------------------------
#define BK   32
#define NS   (D_MODEL / BK)        // 32
#define GST  20                     // u32 words per smem row
#define BUFW (256 * GST)            // A(128) + W(128) rows per buffer
#define GEMM_SMEM (3 * BUFW * 4)    // 61440 B dynamic

struct GemmCtx {
    int m0w, n0w;
    int lrow, a_roff, a_coff, b_roff, b_coff;
};
__device__ __forceinline__ void gemm_stage(const GemmCtx& c, uint32_t ab,
                                           float acc[4][8][4]) {
    const uint32_t wb = ab + 128 * GST * 4;
    #pragma unroll
    for (int ks = 0; ks < 2; ks++) {
        const int k0w = ks * 8;
        uint32_t a[4][4], b[4][4];
        #pragma unroll
        for (int mt = 0; mt < 4; mt++)
            ldm_x4(a[mt], ab + ((c.m0w + mt * 16 + c.a_roff + c.lrow) * GST
                                + k0w + c.a_coff) * 4);
        #pragma unroll
        for (int np = 0; np < 4; np++)
            ldm_x4(b[np], wb + ((c.n0w + np * 16 + c.b_roff + c.lrow) * GST
                                + k0w + c.b_coff) * 4);
        #pragma unroll
        for (int nt = 0; nt < 8; nt++) {
            uint32_t b0 = b[nt >> 1][(nt & 1) * 2];
            uint32_t b1 = b[nt >> 1][(nt & 1) * 2 + 1];
            #pragma unroll
            for (int mt = 0; mt < 4; mt++)
                mma16(acc[mt][nt], a[mt], b0, b1);
        }
    }
}

// ---------------------------------------------------------------------------
// Fused QKV projection GEMM. grid (8, 32, 3), block 128.
// ---------------------------------------------------------------------------
__global__ __launch_bounds__(128, 2) void qkv_gemm_kernel(
    const __half* __restrict__ wt_base,
    const float* __restrict__ bq, const float* __restrict__ bk,
    const float* __restrict__ bv)
{
    extern __shared__ uint32_t sm[];

    const int tid  = threadIdx.x;
    const int w    = tid >> 5, lane = tid & 31;
    const int g    = lane >> 2, t = lane & 3;
    const int bm   = blockIdx.y * 128, bn = blockIdx.x * 128;
    const int bb   = bm >> 11;
    const int z    = blockIdx.z;

    const __half* Wt = wt_base + (size_t)z * D_MODEL * D_MODEL;
    const float* bias = (z == 0) ? bq : (z == 1) ? bk : bv;
    const float alpha = (z == 0) ? 0.125f * 1.4426950408889634f : 1.0f;

    GemmCtx c;
    c.m0w = (w >> 1) * 64; c.n0w = (w & 1) * 64;
    c.lrow = lane & 7;
    c.a_roff = ((lane >> 3) & 1) * 8;
    c.a_coff = (lane >> 4) * 4;
    c.b_roff = (lane >> 4) * 8;
    c.b_coff = ((lane >> 3) & 1) * 4;

    const uint32_t smb = smem_u32(sm);

    auto issue = [&](int kt, int buf) {
        uint32_t dst = smb + buf * (BUFW * 4);
        #pragma unroll
        for (int i = 0; i < 4; i++) {
            int idx = tid + 128 * i;
            int row = idx >> 2, seg = idx & 3;
            cpa16(dst + (row * GST + seg * 4) * 4,
                  g_xh + (size_t)(bm + row) * D_MODEL + kt + seg * 8);
            cpa16(dst + ((128 + row) * GST + seg * 4) * 4,
                  Wt + (size_t)(bn + row) * D_MODEL + kt + seg * 8);
        }
        CPA_COMMIT();
    };

    issue(0, 0);
    issue(BK, 1);

    float acc[4][8][4] = {};

    #pragma unroll 1
    for (int s = 0; s < NS; s++) {
        if (s + 1 < NS) CPA_WAIT1(); else CPA_WAIT0();
        __syncthreads();
        if (s + 2 < NS) issue((s + 2) * BK, (s + 2) % 3);
        gemm_stage(c, smb + (s % 3) * (BUFW * 4), acc);
    }

    __half* outp = (z == 0) ? g_Qh : (z == 1) ? g_Kh : g_Vh;
    #pragma unroll
    for (int mt = 0; mt < 4; mt++) {
        #pragma unroll
        for (int nt = 0; nt < 8; nt++) {
            int rl = c.m0w + mt * 16 + g;
            int cl = c.n0w + nt * 8 + t * 2;
            float2 bv2 = *(const float2*)&bias[bn + cl];
            float v00 = (acc[mt][nt][0] + bv2.x) * alpha;
            float v01 = (acc[mt][nt][1] + bv2.y) * alpha;
            float v10 = (acc[mt][nt][2] + bv2.x) * alpha;
            float v11 = (acc[mt][nt][3] + bv2.y) * alpha;
            int col = bn + cl;
            int h = col >> 6, d = col & 63;
            int t0r = (bm + rl) & (SEQ - 1);
            __half* ob = outp + ((size_t)(bb * NHEAD + h)) * SEQ * DH;
            *(uint32_t*)&ob[(size_t)t0r * DH + d] = pack2(v00, v01);
            *(uint32_t*)&ob[(size_t)(t0r + 8) * DH + d] = pack2(v10, v11);
        }
    }
}

// ---------------------------------------------------------------------------
// Output GEMM: d_out = concat(O) @ Wo + bo. grid (8, 32), block 128.
// ---------------------------------------------------------------------------
__global__ __launch_bounds__(128, 2) void out_gemm_kernel(
    const __half* __restrict__ Wt, const float* __restrict__ bias,
    float* __restrict__ Cout)
{
    extern __shared__ uint32_t sm[];

    const int tid  = threadIdx.x;
    const int w    = tid >> 5, lane = tid & 31;
    const int g    = lane >> 2, t = lane & 3;
    const int bm   = blockIdx.y * 128, bn = blockIdx.x * 128;
    const int bb   = bm >> 11;

    GemmCtx c;
    c.m0w = (w >> 1) * 64; c.n0w = (w & 1) * 64;
    c.lrow = lane & 7;
    c.a_roff = ((lane >> 3) & 1) * 8;
    c.a_coff = (lane >> 4) * 4;
    c.b_roff = (lane >> 4) * 8;
    c.b_coff = ((lane >> 3) & 1) * 4;

    const uint32_t smb = smem_u32(sm);

    auto issue = [&](int kt, int buf) {
        uint32_t dst = smb + buf * (BUFW * 4);
        const int h = kt >> 6, d0 = kt & 63;
        #pragma unroll
        for (int i = 0; i < 4; i++) {
            int idx = tid + 128 * i;
            int row = idx >> 2, seg = idx & 3;
            int tt = (bm + row) & (SEQ - 1);
            cpa16(dst + (row * GST + seg * 4) * 4,
                  g_Oh + (((size_t)(bb * NHEAD + h)) * SEQ + tt) * DH
                  + d0 + seg * 8);
            cpa16(dst + ((128 + row) * GST + seg * 4) * 4,
                  Wt + (size_t)(bn + row) * D_MODEL + kt + seg * 8);
        }
        CPA_COMMIT();
    };

    issue(0, 0);
    issue(BK, 1);

    float acc[4][8][4] = {};

    #pragma unroll 1
    for (int s = 0; s < NS; s++) {
        if (s + 1 < NS) CPA_WAIT1(); else CPA_WAIT0();
        __syncthreads();
        if (s + 2 < NS) issue((s + 2) * BK, (s + 2) % 3);
        gemm_stage(c, smb + (s % 3) * (BUFW * 4), acc);
    }

    #pragma unroll
    for (int mt = 0; mt < 4; mt++) {
        #pragma unroll
        for (int nt = 0; nt < 8; nt++) {
            int rl = c.m0w + mt * 16 + g;
            int cl = c.n0w + nt * 8 + t * 2;
            float2 bv2 = *(const float2*)&bias[bn + cl];
            *(float2*)&Cout[(size_t)(bm + rl) * D_MODEL + bn + cl] =
                make_float2(acc[mt][nt][0] + bv2.x, acc[mt][nt][1] + bv2.y);
            *(float2*)&Cout[(size_t)(bm + rl + 8) * D_MODEL + bn + cl] =
                make_float2(acc[mt][nt][2] + bv2.x, acc[mt][nt][3] + bv2.y);
        }
    }
}

// ---------------------------------------------------------------------------
// Flash attention (R7 config — measured best). CTA = 128 threads (4 warps)
// x 64 queries; 4 CTAs/SM. cp.async double-buffered 64-key KV tiles.
// Softmax in exp2 domain (log2e folded into Q projection).
// ---------------------------------------------------------------------------
#define FST 36
#define KVW (64 * FST)   // words per K (or V) tile

__global__ __launch_bounds__(128, 4) void flash_kernel()
{
    __shared__ uint32_t Ks[2][KVW];   // 18432 B
    __shared__ uint32_t Vs[2][KVW];   // 18432 B

    const int tid = threadIdx.x;
    const int w = tid >> 5, lane = tid & 31;
    const int g = lane >> 2, t = lane & 3;
    const int bh = blockIdx.y;
    const int q0 = blockIdx.x * 64;

    const __half* Qp = g_Qh + ((size_t)bh * SEQ + q0) * DH;
    const __half* Kp = g_Kh + (size_t)bh * SEQ * DH;
    const __half* Vp = g_Vh + (size_t)bh * SEQ * DH;

    const int lr = w * 16 + g;

    // Q fragments in registers (scale incl. log2e folded into projection).
    uint32_t qf[4][4];
    #pragma unroll
    for (int s = 0; s < 4; s++) {
        qf[s][0] = *(const uint32_t*)(Qp + (size_t)lr * DH + s * 16 + 2 * t);
        qf[s][1] = *(const uint32_t*)(Qp + (size_t)(lr + 8) * DH + s * 16 + 2 * t);
        qf[s][2] = *(const uint32_t*)(Qp + (size_t)lr * DH + s * 16 + 8 + 2 * t);
        qf[s][3] = *(const uint32_t*)(Qp + (size_t)(lr + 8) * DH + s * 16 + 8 + 2 * t);
    }

    const uint32_t ksb = smem_u32(Ks), vsb = smem_u32(Vs);
    const int lrow = lane & 7;
    const uint32_t k_lane = ksb + (lrow * FST + (lane >> 3) * 4) * 4;
    const uint32_t v_lane = vsb + ((((lane >> 3) & 1) * 8 + lrow) * FST
                                   + (lane >> 4) * 4) * 4;

    auto issueKV = [&](int kt, int buf) {
        const uint32_t koff = buf * (KVW * 4);
        #pragma unroll
        for (int i = 0; i < 4; i++) {
            int idx = i * 128 + tid;
            int row = idx >> 3, seg = idx & 7;
            cpa16(ksb + koff + (row * FST + seg * 4) * 4,
                  Kp + (size_t)(kt + row) * DH + seg * 8);
            cpa16(vsb + koff + (row * FST + seg * 4) * 4,
                  Vp + (size_t)(kt + row) * DH + seg * 8);
        }
        CPA_COMMIT();
    };

    issueKV(0, 0);

    float o[8][4] = {};
    float m0 = -INFINITY, m1 = -INFINITY, l0 = 0.f, l1 = 0.f;

    #pragma unroll 1
    for (int it = 0; it < SEQ / 64; it++) {
        const int buf = it & 1;
        CPA_WAIT0();
        __syncthreads();
        if (it + 1 < SEQ / 64) issueKV((it + 1) * 64, buf ^ 1);

        const uint32_t kl = k_lane + buf * (KVW * 4);
        const uint32_t vl = v_lane + buf * (KVW * 4);

        // S = Q @ K^T (log2-domain scores)
        float s_[8][4] = {};
        #pragma unroll
        for (int nt = 0; nt < 8; nt++) {
            uint32_t kb[4], kb2[4];
            uint32_t base = kl + nt * 8 * (FST * 4);
            ldm_x4(kb,  base);
            ldm_x4(kb2, base + 16 * 4);
            mma16(s_[nt], qf[0], kb[0],  kb[1]);
            mma16(s_[nt], qf[1], kb[2],  kb[3]);
            mma16(s_[nt], qf[2], kb2[0], kb2[1]);
            mma16(s_[nt], qf[3], kb2[2], kb2[3]);
        }

        // online softmax (exp2 domain)
        float mx0 = -INFINITY, mx1 = -INFINITY;
        #pragma unroll
        for (int nt = 0; nt < 8; nt++) {
            mx0 = fmaxf(mx0, fmaxf(s_[nt][0], s_[nt][1]));
            mx1 = fmaxf(mx1, fmaxf(s_[nt][2], s_[nt][3]));
        }
        mx0 = fmaxf(mx0, __shfl_xor_sync(0xffffffffu, mx0, 1));
        mx0 = fmaxf(mx0, __shfl_xor_sync(0xffffffffu, mx0, 2));
        mx1 = fmaxf(mx1, __shfl_xor_sync(0xffffffffu, mx1, 1));
        mx1 = fmaxf(mx1, __shfl_xor_sync(0xffffffffu, mx1, 2));

        float mn0 = fmaxf(m0, mx0), mn1 = fmaxf(m1, mx1);
        float c0 = exp2f(m0 - mn0), c1 = exp2f(m1 - mn1);
        m0 = mn0; m1 = mn1;

        float sum0 = 0.f, sum1 = 0.f;
        #pragma unroll
        for (int nt = 0; nt < 8; nt++) {
            s_[nt][0] = exp2f(s_[nt][0] - mn0); sum0 += s_[nt][0];
            s_[nt][1] = exp2f(s_[nt][1] - mn0); sum0 += s_[nt][1];
            s_[nt][2] = exp2f(s_[nt][2] - mn1); sum1 += s_[nt][2];
            s_[nt][3] = exp2f(s_[nt][3] - mn1); sum1 += s_[nt][3];
        }
        sum0 += __shfl_xor_sync(0xffffffffu, sum0, 1);
        sum0 += __shfl_xor_sync(0xffffffffu, sum0, 2);
        sum1 += __shfl_xor_sync(0xffffffffu, sum1, 1);
        sum1 += __shfl_xor_sync(0xffffffffu, sum1, 2);
        l0 = l0 * c0 + sum0;
        l1 = l1 * c1 + sum1;

        #pragma unroll
        for (int nt = 0; nt < 8; nt++) {
            o[nt][0] *= c0; o[nt][1] *= c0;
            o[nt][2] *= c1; o[nt][3] *= c1;
        }

        // P frags in registers
        uint32_t pf[4][4];
        #pragma unroll
        for (int s = 0; s < 4; s++) {
            pf[s][0] = pack2(s_[2 * s][0],     s_[2 * s][1]);
            pf[s][1] = pack2(s_[2 * s][2],     s_[2 * s][3]);
            pf[s][2] = pack2(s_[2 * s + 1][0], s_[2 * s + 1][1]);
            pf[s][3] = pack2(s_[2 * s + 1][2], s_[2 * s + 1][3]);
        }

        // O += P @ V
        #pragma unroll
        for (int s = 0; s < 4; s++) {
            uint32_t base = vl + s * 16 * (FST * 4);
            #pragma unroll
            for (int np = 0; np < 4; np++) {
                uint32_t vb[4];
                ldm_x4_t(vb, base + np * 8 * 4);
                mma16(o[2 * np],     pf[s], vb[0], vb[1]);
                mma16(o[2 * np + 1], pf[s], vb[2], vb[3]);
            }
        }
    }

    // epilogue -> g_Oh
    float inv0 = 1.0f / l0, inv1 = 1.0f / l1;
    __half* Op = g_Oh + ((size_t)bh * SEQ + q0) * DH;
    #pragma unroll
    for (int nt = 0; nt < 8; nt++) {
        int col = nt * 8 + t * 2;
        *(uint32_t*)&Op[(size_t)lr * DH + col] =
            pack2(o[nt][0] * inv0, o[nt][1] * inv0);
        *(uint32_t*)&Op[(size_t)(lr + 8) * DH + col] =
            pack2(o[nt][2] * inv1, o[nt][3] * inv1);
    }
}

// ---------------------------------------------------------------------------
extern "C" void kernel_launch(void* const* d_in, const int* in_sizes, int n_in,
                              void* d_out, int out_size)
{
    const float* x  = (const float*)d_in[0];
    const float* Wq = (const float*)d_in[1];
    const float* bq = (const float*)d_in[2];
    const float* Wk = (const float*)d_in[3];
    const float* bk = (const float*)d_in[4];
    const float* Wv = (const float*)d_in[5];
    const float* bv = (const float*)d_in[6];
    const float* Wo = (const float*)d_in[7];
    const float* bo = (const float*)d_in[8];
    (void)in_sizes; (void)n_in; (void)out_size;

    static __half* wt_base = nullptr;
    if (!wt_base) {
        void* p = nullptr;
        cudaGetSymbolAddress(&p, g_Wt);
        wt_base = (__half*)p;
        cudaFuncSetAttribute(qkv_gemm_kernel,
            cudaFuncAttributeMaxDynamicSharedMemorySize, GEMM_SMEM);
        cudaFuncSetAttribute(out_gemm_kernel,
            cudaFuncAttributeMaxDynamicSharedMemorySize, GEMM_SMEM);
    }
    const size_t WSZ = (size_t)D_MODEL * D_MODEL;

    conv_x_kernel<<<MROWS * D_MODEL / 1024, 256>>>(x);
    transpose_w_kernel<<<dim3(D_MODEL / 32, D_MODEL / 32, 4), 256>>>(
        Wq, Wk, Wv, Wo);

    qkv_gemm_kernel<<<dim3(D_MODEL / 128, MROWS / 128, 3), 128, GEMM_SMEM>>>(
        wt_base, bq, bk, bv);

    flash_kernel<<<dim3(SEQ / 64, BHN), 128>>>();

    out_gemm_kernel<<<dim3(D_MODEL / 128, MROWS / 128), 128, GEMM_SMEM>>>(
        wt_base + 3 * WSZ, bo, (float*)d_out);
}

// round 10
// speedup vs baseline: 4.1365x; 1.0372x over previous
#include <cuda_runtime.h>
#include <cuda_fp16.h>
#include <math.h>
#include <stdint.h>

#define D_MODEL 1024
#define NHEAD   16
#define DH      64
#define BATCH   2
#define SEQ     2048
#define MROWS   (BATCH*SEQ)   // 4096
#define BHN     (BATCH*NHEAD) // 32

// Scratch (allocation-free): fp16 buffers.
__device__ __align__(16) __half g_Qh[BHN * SEQ * DH];
__device__ __align__(16) __half g_Kh[BHN * SEQ * DH];
__device__ __align__(16) __half g_Vh[BHN * SEQ * DH];
__device__ __align__(16) __half g_Oh[BHN * SEQ * DH];
__device__ __align__(16) __half g_xh[MROWS * D_MODEL];
__device__ __align__(16) __half g_Wt[4][D_MODEL * D_MODEL];  // [n][k] fp16

// ---------------------------------------------------------------------------
// helpers
// ---------------------------------------------------------------------------
__device__ __forceinline__ uint32_t pack2(float a, float b) {
    __half2 h = __floats2half2_rn(a, b);
    return *reinterpret_cast<uint32_t*>(&h);
}
__device__ __forceinline__ uint32_t h2exp2(uint32_t x) {
    uint32_t r;
    asm volatile("ex2.approx.f16x2 %0, %1;" : "=r"(r) : "r"(x));
    return r;
}
__device__ __forceinline__ uint32_t smem_u32(const void* p) {
    uint32_t r;
    asm("{ .reg .u64 t; cvta.to.shared.u64 t, %1; cvt.u32.u64 %0, t; }"
        : "=r"(r) : "l"(p));
    return r;
}
__device__ __forceinline__ void mma16(float* c, const uint32_t* a,
                                      uint32_t b0, uint32_t b1) {
    asm volatile(
        "mma.sync.aligned.m16n8k16.row.col.f32.f16.f16.f32 "
        "{%0,%1,%2,%3}, {%4,%5,%6,%7}, {%8,%9}, {%0,%1,%2,%3};"
        : "+f"(c[0]), "+f"(c[1]), "+f"(c[2]), "+f"(c[3])
        : "r"(a[0]), "r"(a[1]), "r"(a[2]), "r"(a[3]), "r"(b0), "r"(b1));
}
__device__ __forceinline__ void ldm_x4(uint32_t* r, uint32_t addr) {
    asm volatile("ldmatrix.sync.aligned.m8n8.x4.shared.b16 {%0,%1,%2,%3}, [%4];"
        : "=r"(r[0]), "=r"(r[1]), "=r"(r[2]), "=r"(r[3]) : "r"(addr));
}
__device__ __forceinline__ void ldm_x4_t(uint32_t* r, uint32_t addr) {
    asm volatile("ldmatrix.sync.aligned.m8n8.x4.trans.shared.b16 {%0,%1,%2,%3}, [%4];"
        : "=r"(r[0]), "=r"(r[1]), "=r"(r[2]), "=r"(r[3]) : "r"(addr));
}
__device__ __forceinline__ void cpa16(uint32_t dst, const void* src) {
    asm volatile("cp.async.cg.shared.global [%0], [%1], 16;"
                 :: "r"(dst), "l"(src) : "memory");
}
#define CPA_COMMIT() asm volatile("cp.async.commit_group;" ::: "memory")
#define CPA_WAIT0()  asm volatile("cp.async.wait_group 0;" ::: "memory")
#define CPA_WAIT1()  asm volatile("cp.async.wait_group 1;" ::: "memory")

// ---------------------------------------------------------------------------
// Pre-pass: x (f32) -> g_xh (f16)
// ---------------------------------------------------------------------------
__global__ __launch_bounds__(256) void conv_x_kernel(const float* __restrict__ x)
{
    int idx = blockIdx.x * 256 + threadIdx.x;
    float4 v = *(const float4*)(x + (size_t)idx * 4);
    uint2 u = make_uint2(pack2(v.x, v.y), pack2(v.z, v.w));
    *(uint2*)(g_xh + (size_t)idx * 4) = u;
}

// ---------------------------------------------------------------------------
// Pre-pass: all 4 weights [k][n] f32 -> g_Wt[z] [n][k] f16. 32x32 tiles.
// ---------------------------------------------------------------------------
__global__ __launch_bounds__(256) void transpose_w_kernel(
    const float* __restrict__ W0, const float* __restrict__ W1,
    const float* __restrict__ W2, const float* __restrict__ W3)
{
    __shared__ float tile[32][33];
    const int z = blockIdx.z;
    const float* W = (z == 0) ? W0 : (z == 1) ? W1 : (z == 2) ? W2 : W3;
    const int tx = threadIdx.x & 31, ty = threadIdx.x >> 5;  // (32, 8)
    const int k0 = blockIdx.y * 32, n0 = blockIdx.x * 32;
    #pragma unroll
    for (int j = 0; j < 4; j++)
        tile[ty + 8 * j][tx] = W[(size_t)(k0 + ty + 8 * j) * D_MODEL + n0 + tx];
    __syncthreads();
    __half* Wt = g_Wt[z];
    #pragma unroll
    for (int jj = 0; jj < 2; jj++) {
        int w_ = threadIdx.x + 256 * jj;   // 0..511
        int n = w_ >> 4, c = w_ & 15;
        uint32_t u = pack2(tile[2 * c][n], tile[2 * c + 1][n]);
        *(uint32_t*)(Wt + (size_t)(n0 + n) * D_MODEL + k0 + 2 * c) = u;
    }
}

// ---------------------------------------------------------------------------
// GEMM geometry: CTA 128x128, 128 threads (4 warps, 2x2), warp tile 64x64.
// BK=32, 3-stage cp.async pipeline. (measured good — unchanged)
// ---------------------------------------------------------------------------
#define BK   32
#define NS   (D_MODEL / BK)        // 32
#define GST  20                     // u32 words per smem row
#define BUFW (256 * GST)            // A(128) + W(128) rows per buffer
#define GEMM_SMEM (3 * BUFW * 4)    // 61440 B dynamic

struct GemmCtx {
    int m0w, n0w;
    int lrow, a_roff, a_coff, b_roff, b_coff;
};
__device__ __forceinline__ void gemm_stage(const GemmCtx& c, uint32_t ab,
                                           float acc[4][8][4]) {
    const uint32_t wb = ab + 128 * GST * 4;
    #pragma unroll
    for (int ks = 0; ks < 2; ks++) {
        const int k0w = ks * 8;
        uint32_t a[4][4], b[4][4];
        #pragma unroll
        for (int mt = 0; mt < 4; mt++)
            ldm_x4(a[mt], ab + ((c.m0w + mt * 16 + c.a_roff + c.lrow) * GST
                                + k0w + c.a_coff) * 4);
        #pragma unroll
        for (int np = 0; np < 4; np++)
            ldm_x4(b[np], wb + ((c.n0w + np * 16 + c.b_roff + c.lrow) * GST
                                + k0w + c.b_coff) * 4);
        #pragma unroll
        for (int nt = 0; nt < 8; nt++) {
            uint32_t b0 = b[nt >> 1][(nt & 1) * 2];
            uint32_t b1 = b[nt >> 1][(nt & 1) * 2 + 1];
            #pragma unroll
            for (int mt = 0; mt < 4; mt++)
                mma16(acc[mt][nt], a[mt], b0, b1);
        }
    }
}

// ---------------------------------------------------------------------------
// Fused QKV projection GEMM. grid (8, 32, 3), block 128.
// ---------------------------------------------------------------------------
__global__ __launch_bounds__(128, 2) void qkv_gemm_kernel(
    const __half* __restrict__ wt_base,
    const float* __restrict__ bq, const float* __restrict__ bk,
    const float* __restrict__ bv)
{
    extern __shared__ uint32_t sm[];

    const int tid  = threadIdx.x;
    const int w    = tid >> 5, lane = tid & 31;
    const int g    = lane >> 2, t = lane & 3;
    const int bm   = blockIdx.y * 128, bn = blockIdx.x * 128;
    const int bb   = bm >> 11;
    const int z    = blockIdx.z;

    const __half* Wt = wt_base + (size_t)z * D_MODEL * D_MODEL;
    const float* bias = (z == 0) ? bq : (z == 1) ? bk : bv;
    const float alpha = (z == 0) ? 0.125f * 1.4426950408889634f : 1.0f;

    GemmCtx c;
    c.m0w = (w >> 1) * 64; c.n0w = (w & 1) * 64;
    c.lrow = lane & 7;
    c.a_roff = ((lane >> 3) & 1) * 8;
    c.a_coff = (lane >> 4) * 4;
    c.b_roff = (lane >> 4) * 8;
    c.b_coff = ((lane >> 3) & 1) * 4;

    const uint32_t smb = smem_u32(sm);

    auto issue = [&](int kt, int buf) {
        uint32_t dst = smb + buf * (BUFW * 4);
        #pragma unroll
        for (int i = 0; i < 4; i++) {
            int idx = tid + 128 * i;
            int row = idx >> 2, seg = idx & 3;
            cpa16(dst + (row * GST + seg * 4) * 4,
                  g_xh + (size_t)(bm + row) * D_MODEL + kt + seg * 8);
            cpa16(dst + ((128 + row) * GST + seg * 4) * 4,
                  Wt + (size_t)(bn + row) * D_MODEL + kt + seg * 8);
        }
        CPA_COMMIT();
    };

    issue(0, 0);
    issue(BK, 1);

    float acc[4][8][4] = {};

    #pragma unroll 1
    for (int s = 0; s < NS; s++) {
        if (s + 1 < NS) CPA_WAIT1(); else CPA_WAIT0();
        __syncthreads();
        if (s + 2 < NS) issue((s + 2) * BK, (s + 2) % 3);
        gemm_stage(c, smb + (s % 3) * (BUFW * 4), acc);
    }

    __half* outp = (z == 0) ? g_Qh : (z == 1) ? g_Kh : g_Vh;
    #pragma unroll
    for (int mt = 0; mt < 4; mt++) {
        #pragma unroll
        for (int nt = 0; nt < 8; nt++) {
            int rl = c.m0w + mt * 16 + g;
            int cl = c.n0w + nt * 8 + t * 2;
            float2 bv2 = *(const float2*)&bias[bn + cl];
            float v00 = (acc[mt][nt][0] + bv2.x) * alpha;
            float v01 = (acc[mt][nt][1] + bv2.y) * alpha;
            float v10 = (acc[mt][nt][2] + bv2.x) * alpha;
            float v11 = (acc[mt][nt][3] + bv2.y) * alpha;
            int col = bn + cl;
            int h = col >> 6, d = col & 63;
            int t0r = (bm + rl) & (SEQ - 1);
            __half* ob = outp + ((size_t)(bb * NHEAD + h)) * SEQ * DH;
            *(uint32_t*)&ob[(size_t)t0r * DH + d] = pack2(v00, v01);
            *(uint32_t*)&ob[(size_t)(t0r + 8) * DH + d] = pack2(v10, v11);
        }
    }
}

// ---------------------------------------------------------------------------
// Output GEMM: d_out = concat(O) @ Wo + bo. grid (8, 32), block 128.
// ---------------------------------------------------------------------------
__global__ __launch_bounds__(128, 2) void out_gemm_kernel(
    const __half* __restrict__ Wt, const float* __restrict__ bias,
    float* __restrict__ Cout)
{
    extern __shared__ uint32_t sm[];

    const int tid  = threadIdx.x;
    const int w    = tid >> 5, lane = tid & 31;
    const int g    = lane >> 2, t = lane & 3;
    const int bm   = blockIdx.y * 128, bn = blockIdx.x * 128;
    const int bb   = bm >> 11;

    GemmCtx c;
    c.m0w = (w >> 1) * 64; c.n0w = (w & 1) * 64;
    c.lrow = lane & 7;
    c.a_roff = ((lane >> 3) & 1) * 8;
    c.a_coff = (lane >> 4) * 4;
    c.b_roff = (lane >> 4) * 8;
    c.b_coff = ((lane >> 3) & 1) * 4;

    const uint32_t smb = smem_u32(sm);

    auto issue = [&](int kt, int buf) {
        uint32_t dst = smb + buf * (BUFW * 4);
        const int h = kt >> 6, d0 = kt & 63;
        #pragma unroll
        for (int i = 0; i < 4; i++) {
            int idx = tid + 128 * i;
            int row = idx >> 2, seg = idx & 3;
            int tt = (bm + row) & (SEQ - 1);
            cpa16(dst + (row * GST + seg * 4) * 4,
                  g_Oh + (((size_t)(bb * NHEAD + h)) * SEQ + tt) * DH
                  + d0 + seg * 8);
            cpa16(dst + ((128 + row) * GST + seg * 4) * 4,
                  Wt + (size_t)(bn + row) * D_MODEL + kt + seg * 8);
        }
        CPA_COMMIT();
    };

    issue(0, 0);
    issue(BK, 1);

    float acc[4][8][4] = {};

    #pragma unroll 1
    for (int s = 0; s < NS; s++) {
        if (s + 1 < NS) CPA_WAIT1(); else CPA_WAIT0();
        __syncthreads();
        if (s + 2 < NS) issue((s + 2) * BK, (s + 2) % 3);
        gemm_stage(c, smb + (s % 3) * (BUFW * 4), acc);
    }

    #pragma unroll
    for (int mt = 0; mt < 4; mt++) {
        #pragma unroll
        for (int nt = 0; nt < 8; nt++) {
            int rl = c.m0w + mt * 16 + g;
            int cl = c.n0w + nt * 8 + t * 2;
            float2 bv2 = *(const float2*)&bias[bn + cl];
            *(float2*)&Cout[(size_t)(bm + rl) * D_MODEL + bn + cl] =
                make_float2(acc[mt][nt][0] + bv2.x, acc[mt][nt][1] + bv2.y);
            *(float2*)&Cout[(size_t)(bm + rl + 8) * D_MODEL + bn + cl] =
                make_float2(acc[mt][nt][2] + bv2.x, acc[mt][nt][3] + bv2.y);
        }
    }
}

// ---------------------------------------------------------------------------
// Flash attention. CTA = 128 threads (4 warps) x 64 queries; 4 CTAs/SM.
// cp.async double-buffered 64-key KV tiles; exp2-domain softmax with
// ex2.approx.f16x2 (P computed directly in fp16) and row-sums l via an
// extra MMA against a constant all-ones B fragment (exact fp32 sums).
// ---------------------------------------------------------------------------
#define FST 36
#define KVW (64 * FST)   // words per K (or V) tile
#define H2_ONES 0x3C003C00u

__global__ __launch_bounds__(128, 4) void flash_kernel()
{
    __shared__ uint32_t Ks[2][KVW];   // 18432 B
    __shared__ uint32_t Vs[2][KVW];   // 18432 B

    const int tid = threadIdx.x;
    const int w = tid >> 5, lane = tid & 31;
    const int g = lane >> 2, t = lane & 3;
    const int bh = blockIdx.y;
    const int q0 = blockIdx.x * 64;

    const __half* Qp = g_Qh + ((size_t)bh * SEQ + q0) * DH;
    const __half* Kp = g_Kh + (size_t)bh * SEQ * DH;
    const __half* Vp = g_Vh + (size_t)bh * SEQ * DH;

    const int lr = w * 16 + g;

    // Q fragments in registers (scale incl. log2e folded into projection).
    uint32_t qf[4][4];
    #pragma unroll
    for (int s = 0; s < 4; s++) {
        qf[s][0] = *(const uint32_t*)(Qp + (size_t)lr * DH + s * 16 + 2 * t);
        qf[s][1] = *(const uint32_t*)(Qp + (size_t)(lr + 8) * DH + s * 16 + 2 * t);
        qf[s][2] = *(const uint32_t*)(Qp + (size_t)lr * DH + s * 16 + 8 + 2 * t);
        qf[s][3] = *(const uint32_t*)(Qp + (size_t)(lr + 8) * DH + s * 16 + 8 + 2 * t);
    }

    const uint32_t ksb = smem_u32(Ks), vsb = smem_u32(Vs);
    const int lrow = lane & 7;
    const uint32_t k_lane = ksb + (lrow * FST + (lane >> 3) * 4) * 4;
    const uint32_t v_lane = vsb + ((((lane >> 3) & 1) * 8 + lrow) * FST
                                   + (lane >> 4) * 4) * 4;

    auto issueKV = [&](int kt, int buf) {
        const uint32_t koff = buf * (KVW * 4);
        #pragma unroll
        for (int i = 0; i < 4; i++) {
            int idx = i * 128 + tid;
            int row = idx >> 3, seg = idx & 7;
            cpa16(ksb + koff + (row * FST + seg * 4) * 4,
                  Kp + (size_t)(kt + row) * DH + seg * 8);
            cpa16(vsb + koff + (row * FST + seg * 4) * 4,
                  Vp + (size_t)(kt + row) * DH + seg * 8);
        }
        CPA_COMMIT();
    };

    issueKV(0, 0);

    float o[8][4] = {};
    float lsum[4] = {};
    float m0 = -INFINITY, m1 = -INFINITY;

    #pragma unroll 1
    for (int it = 0; it < SEQ / 64; it++) {
        const int buf = it & 1;
        CPA_WAIT0();
        __syncthreads();
        if (it + 1 < SEQ / 64) issueKV((it + 1) * 64, buf ^ 1);

        const uint32_t kl = k_lane + buf * (KVW * 4);
        const uint32_t vl = v_lane + buf * (KVW * 4);

        // S = Q @ K^T (log2-domain scores)
        float s_[8][4] = {};
        #pragma unroll
        for (int nt = 0; nt < 8; nt++) {
            uint32_t kb[4], kb2[4];
            uint32_t base = kl + nt * 8 * (FST * 4);
            ldm_x4(kb,  base);
            ldm_x4(kb2, base + 16 * 4);
            mma16(s_[nt], qf[0], kb[0],  kb[1]);
            mma16(s_[nt], qf[1], kb[2],  kb[3]);
            mma16(s_[nt], qf[2], kb2[0], kb2[1]);
            mma16(s_[nt], qf[3], kb2[2], kb2[3]);
        }

        // online softmax: row max
        float mx0 = -INFINITY, mx1 = -INFINITY;
        #pragma unroll
        for (int nt = 0; nt < 8; nt++) {
            mx0 = fmaxf(mx0, fmaxf(s_[nt][0], s_[nt][1]));
            mx1 = fmaxf(mx1, fmaxf(s_[nt][2], s_[nt][3]));
        }
        mx0 = fmaxf(mx0, __shfl_xor_sync(0xffffffffu, mx0, 1));
        mx0 = fmaxf(mx0, __shfl_xor_sync(0xffffffffu, mx0, 2));
        mx1 = fmaxf(mx1, __shfl_xor_sync(0xffffffffu, mx1, 1));
        mx1 = fmaxf(mx1, __shfl_xor_sync(0xffffffffu, mx1, 2));

        float mn0 = fmaxf(m0, mx0), mn1 = fmaxf(m1, mx1);
        float c0 = exp2f(m0 - mn0), c1 = exp2f(m1 - mn1);
        m0 = mn0; m1 = mn1;

        // P directly in fp16: pack (s - m) pairs, ex2.approx.f16x2.
        // pf[s] keeps the PV A-frag layout: [0]=row lr lo-k, [1]=row lr+8
        // lo-k, [2]=row lr hi-k, [3]=row lr+8 hi-k.
        uint32_t pf[4][4];
        #pragma unroll
        for (int s = 0; s < 4; s++) {
            pf[s][0] = h2exp2(pack2(s_[2 * s][0] - mn0,     s_[2 * s][1] - mn0));
            pf[s][1] = h2exp2(pack2(s_[2 * s][2] - mn1,     s_[2 * s][3] - mn1));
            pf[s][2] = h2exp2(pack2(s_[2 * s + 1][0] - mn0, s_[2 * s + 1][1] - mn0));
            pf[s][3] = h2exp2(pack2(s_[2 * s + 1][2] - mn1, s_[2 * s + 1][3] - mn1));
        }

        // rescale running O and l
        #pragma unroll
        for (int nt = 0; nt < 8; nt++) {
            o[nt][0] *= c0; o[nt][1] *= c0;
            o[nt][2] *= c1; o[nt][3] *= c1;
        }
        lsum[0] *= c0; lsum[1] *= c0; lsum[2] *= c1; lsum[3] *= c1;

        // l += P @ ones  (constant B fragment — no ldmatrix, exact fp32 sum)
        #pragma unroll
        for (int s = 0; s < 4; s++)
            mma16(lsum, pf[s], H2_ONES, H2_ONES);

        // O += P @ V
        #pragma unroll
        for (int s = 0; s < 4; s++) {
            uint32_t base = vl + s * 16 * (FST * 4);
            #pragma unroll
            for (int np = 0; np < 4; np++) {
                uint32_t vb[4];
                ldm_x4_t(vb, base + np * 8 * 4);
                mma16(o[2 * np],     pf[s], vb[0], vb[1]);
                mma16(o[2 * np + 1], pf[s], vb[2], vb[3]);
            }
        }
    }

    // epilogue -> g_Oh   (lsum[0]: row lr, lsum[2]: row lr+8)
    float inv0 = 1.0f / lsum[0], inv1 = 1.0f / lsum[2];
    __half* Op = g_Oh + ((size_t)bh * SEQ + q0) * DH;
    #pragma unroll
    for (int nt = 0; nt < 8; nt++) {
        int col = nt * 8 + t * 2;
        *(uint32_t*)&Op[(size_t)lr * DH + col] =
            pack2(o[nt][0] * inv0, o[nt][1] * inv0);
        *(uint32_t*)&Op[(size_t)(lr + 8) * DH + col] =
            pack2(o[nt][2] * inv1, o[nt][3] * inv1);
    }
}

// ---------------------------------------------------------------------------
extern "C" void kernel_launch(void* const* d_in, const int* in_sizes, int n_in,
                              void* d_out, int out_size)
{
    const float* x  = (const float*)d_in[0];
    const float* Wq = (const float*)d_in[1];
    const float* bq = (const float*)d_in[2];
    const float* Wk = (const float*)d_in[3];
    const float* bk = (const float*)d_in[4];
    const float* Wv = (const float*)d_in[5];
    const float* bv = (const float*)d_in[6];
    const float* Wo = (const float*)d_in[7];
    const float* bo = (const float*)d_in[8];
    (void)in_sizes; (void)n_in; (void)out_size;

    static __half* wt_base = nullptr;
    if (!wt_base) {
        void* p = nullptr;
        cudaGetSymbolAddress(&p, g_Wt);
        wt_base = (__half*)p;
        cudaFuncSetAttribute(qkv_gemm_kernel,
            cudaFuncAttributeMaxDynamicSharedMemorySize, GEMM_SMEM);
        cudaFuncSetAttribute(out_gemm_kernel,
            cudaFuncAttributeMaxDynamicSharedMemorySize, GEMM_SMEM);
    }
    const size_t WSZ = (size_t)D_MODEL * D_MODEL;

    conv_x_kernel<<<MROWS * D_MODEL / 1024, 256>>>(x);
    transpose_w_kernel<<<dim3(D_MODEL / 32, D_MODEL / 32, 4), 256>>>(
        Wq, Wk, Wv, Wo);

    qkv_gemm_kernel<<<dim3(D_MODEL / 128, MROWS / 128, 3), 128, GEMM_SMEM>>>(
        wt_base, bq, bk, bv);

    flash_kernel<<<dim3(SEQ / 64, BHN), 128>>>();

    out_gemm_kernel<<<dim3(D_MODEL / 128, MROWS / 128), 128, GEMM_SMEM>>>(
        wt_base + 3 * WSZ, bo, (float*)d_out);
}